// round 1
// baseline (speedup 1.0000x reference)
#include <cuda_runtime.h>
#include <cstddef>

// Problem constants
#define NN 32768
#define CCH 384
#define EE 384
#define GG 12
#define DD 32
#define PPAIR 16
#define NGRAPH 64

// ---------------------------------------------------------------------------
// Scratch (device globals; no allocation allowed)
// ---------------------------------------------------------------------------
__device__ float g_q[(size_t)NN * EE];    // q_raw -> q_rot
__device__ float g_k[(size_t)NN * EE];    // k_rot, later reused as attn
__device__ float g_v[(size_t)NN * EE];    // v
__device__ float g_kv[(size_t)NGRAPH * GG * DD * DD];
__device__ int   g_off[NGRAPH + 1];

// ---------------------------------------------------------------------------
// Classic fp32 tiled GEMM: C[M,Nc] = A[M,K] @ B[K,Nc] + bias[Nc]
// BM=128, BN=128, BK=8, 256 threads, 8x8 per-thread microtile.
// ---------------------------------------------------------------------------
#define BM 128
#define BN 128
#define BK 8
#define TM 8
#define TN 8

__global__ __launch_bounds__(256, 2) void sgemm_bias(
    const float* __restrict__ A, const float* __restrict__ B,
    const float* __restrict__ bias, float* __restrict__ C,
    int M, int K, int Nc)
{
    __shared__ float As[BK][BM + 4];   // padded: conflict-free transposed stores
    __shared__ float Bs[BK][BN];

    const int tid  = threadIdx.x;
    const int bn   = blockIdx.x * BN;
    const int bm   = blockIdx.y * BM;
    const int trow = (tid >> 4) * TM;   // 0..120
    const int tcol = (tid & 15) * TN;   // 0..120

    const int aRow = tid >> 1;          // 0..127
    const int aCol = (tid & 1) << 2;    // 0 or 4
    const int bRow = tid >> 5;          // 0..7
    const int bCol = (tid & 31) << 2;   // 0..124

    const float* Ap = A + (size_t)(bm + aRow) * K + aCol;
    const float* Bp = B + (size_t)bRow * Nc + bn + bCol;

    float acc[TM][TN];
#pragma unroll
    for (int i = 0; i < TM; i++)
#pragma unroll
        for (int j = 0; j < TN; j++) acc[i][j] = 0.f;

    for (int k0 = 0; k0 < K; k0 += BK) {
        float4 a4 = *(const float4*)(Ap + k0);
        float4 b4 = *(const float4*)(Bp + (size_t)k0 * Nc);
        As[aCol + 0][aRow] = a4.x;
        As[aCol + 1][aRow] = a4.y;
        As[aCol + 2][aRow] = a4.z;
        As[aCol + 3][aRow] = a4.w;
        *(float4*)&Bs[bRow][bCol] = b4;
        __syncthreads();

#pragma unroll
        for (int k = 0; k < BK; k++) {
            float ra[TM], rb[TN];
            *(float4*)&ra[0] = *(const float4*)&As[k][trow];
            *(float4*)&ra[4] = *(const float4*)&As[k][trow + 4];
            *(float4*)&rb[0] = *(const float4*)&Bs[k][tcol];
            *(float4*)&rb[4] = *(const float4*)&Bs[k][tcol + 4];
#pragma unroll
            for (int i = 0; i < TM; i++)
#pragma unroll
                for (int j = 0; j < TN; j++)
                    acc[i][j] += ra[i] * rb[j];
        }
        __syncthreads();
    }

    // epilogue with bias
    float bb[TN];
#pragma unroll
    for (int j = 0; j < TN; j++) bb[j] = bias[bn + tcol + j];
#pragma unroll
    for (int i = 0; i < TM; i++) {
        int row = bm + trow + i;
        float4 o0, o1;
        o0.x = acc[i][0] + bb[0]; o0.y = acc[i][1] + bb[1];
        o0.z = acc[i][2] + bb[2]; o0.w = acc[i][3] + bb[3];
        o1.x = acc[i][4] + bb[4]; o1.y = acc[i][5] + bb[5];
        o1.z = acc[i][6] + bb[6]; o1.w = acc[i][7] + bb[7];
        *(float4*)&C[(size_t)row * Nc + bn + tcol]     = o0;
        *(float4*)&C[(size_t)row * Nc + bn + tcol + 4] = o1;
    }
}

// ---------------------------------------------------------------------------
// RoPE: one thread per (node, group). In-place rotate g_q; write g_k = rope(1).
// ---------------------------------------------------------------------------
__global__ void rope_kernel(const float* __restrict__ pos,
                            const float* __restrict__ freqs)
{
    int idx = blockIdx.x * blockDim.x + threadIdx.x;
    if (idx >= NN * GG) return;
    int n = idx / GG;
    int g = idx % GG;

    float px = pos[n * 3 + 0];
    float py = pos[n * 3 + 1];
    float pz = pos[n * 3 + 2];

    size_t base = (size_t)n * EE + g * DD;
    float qv[DD], qo[DD], ko[DD];
    const float4* qp = (const float4*)(g_q + base);
#pragma unroll
    for (int i = 0; i < DD / 4; i++) ((float4*)qv)[i] = qp[i];

#pragma unroll
    for (int p = 0; p < PPAIR; p++) {
        const float* f = freqs + ((size_t)g * PPAIR + p) * 3;
        float ph = px * f[0] + py * f[1] + pz * f[2];
        float c = __cosf(ph);
        float s = __sinf(ph);
        float x1 = qv[2 * p], x2 = qv[2 * p + 1];
        qo[2 * p]     = x1 * c - x2 * s;
        qo[2 * p + 1] = x1 * s + x2 * c;
        ko[2 * p]     = c - s;     // rope applied to (1,1)
        ko[2 * p + 1] = s + c;
    }
    float4* qw = (float4*)(g_q + base);
    float4* kw = (float4*)(g_k + base);
#pragma unroll
    for (int i = 0; i < DD / 4; i++) {
        qw[i] = ((float4*)qo)[i];
        kw[i] = ((float4*)ko)[i];
    }
}

// ---------------------------------------------------------------------------
// Segment offsets via binary search on sorted batch[]
// ---------------------------------------------------------------------------
__global__ void offsets_kernel(const int* __restrict__ batch, int n)
{
    int t = threadIdx.x;
    if (t > NGRAPH) return;
    if (t == NGRAPH) { g_off[NGRAPH] = n; return; }
    int lo = 0, hi = n;
    while (lo < hi) {
        int mid = (lo + hi) >> 1;
        if (batch[mid] < t) lo = mid + 1; else hi = mid;
    }
    g_off[t] = lo;
}

// ---------------------------------------------------------------------------
// KV segment reduction: block = (group gi, graph b). kv[d][e] = sum_n k[d]*v[e]
// ---------------------------------------------------------------------------
#define KVCH 8
__global__ __launch_bounds__(256) void kv_kernel()
{
    int gi = blockIdx.x;
    int b  = blockIdx.y;
    int s = g_off[b], e = g_off[b + 1];
    int tid = threadIdx.x;

    __shared__ float sk[KVCH][DD];
    __shared__ float sv[KVCH][DD];

    float a0 = 0.f, a1 = 0.f, a2 = 0.f, a3 = 0.f;
    int d  = tid >> 3;          // 0..31
    int e0 = (tid & 7) << 2;    // 0..28

    for (int n0 = s; n0 < e; n0 += KVCH) {
        int cnt = min(KVCH, e - n0);
        __syncthreads();
        for (int i = tid; i < cnt * DD; i += 256) {
            int nn = i >> 5, dd = i & 31;
            size_t off = (size_t)(n0 + nn) * EE + gi * DD + dd;
            sk[nn][dd] = g_k[off];
            sv[nn][dd] = g_v[off];
        }
        __syncthreads();
        for (int c = 0; c < cnt; c++) {
            float kd = sk[c][d];
            a0 += kd * sv[c][e0 + 0];
            a1 += kd * sv[c][e0 + 1];
            a2 += kd * sv[c][e0 + 2];
            a3 += kd * sv[c][e0 + 3];
        }
    }
    const float inv = 1.0f / 512.0f;   // avg_num_nodes = 32768/64
    float* dst = g_kv + (((size_t)b * GG + gi) * DD + d) * DD + e0;
    dst[0] = a0 * inv; dst[1] = a1 * inv; dst[2] = a2 * inv; dst[3] = a3 * inv;
}

// ---------------------------------------------------------------------------
// Apply: attn[n, g*32+e] = sum_d q[n,g*32+d] * kv[batch[n],g,d,e]
// Block = (chunk c, graph b); 128 nodes/chunk; attn written into g_k (reuse).
// ---------------------------------------------------------------------------
#define ACH 128
__global__ __launch_bounds__(256) void attn_kernel()
{
    int c = blockIdx.x;
    int b = blockIdx.y;
    int s = g_off[b], e = g_off[b + 1];
    int nbase = s + c * ACH;
    if (nbase >= e) return;
    int cnt = min(ACH, e - nbase);
    int tid = threadIdx.x;

    __shared__ float Qs[DD][ACH + 4];   // transposed, padded
    __shared__ float Ks[DD][DD];

    int trow = (tid >> 3) * 4;   // 0..124 (node-local)
    int tcol = (tid & 7) * 4;    // 0..28  (e)

    for (int g = 0; g < GG; g++) {
        __syncthreads();
        for (int i = tid; i < ACH * DD; i += 256) {
            int nn = i >> 5, kk = i & 31;
            Qs[kk][nn] = (nn < cnt)
                ? g_q[(size_t)(nbase + nn) * EE + g * DD + kk] : 0.f;
        }
        {
            const float* kvp = g_kv + ((size_t)b * GG + g) * DD * DD;
            for (int i = tid; i < DD * DD; i += 256)
                (&Ks[0][0])[i] = kvp[i];
        }
        __syncthreads();

        float acc[4][4];
#pragma unroll
        for (int i = 0; i < 4; i++)
#pragma unroll
            for (int j = 0; j < 4; j++) acc[i][j] = 0.f;

#pragma unroll
        for (int k = 0; k < DD; k++) {
            float ra[4], rb[4];
            *(float4*)ra = *(const float4*)&Qs[k][trow];
            *(float4*)rb = *(const float4*)&Ks[k][tcol];
#pragma unroll
            for (int i = 0; i < 4; i++)
#pragma unroll
                for (int j = 0; j < 4; j++)
                    acc[i][j] += ra[i] * rb[j];
        }

#pragma unroll
        for (int i = 0; i < 4; i++) {
            int r = trow + i;
            if (r < cnt) {
                float4 o;
                o.x = acc[i][0]; o.y = acc[i][1];
                o.z = acc[i][2]; o.w = acc[i][3];
                *(float4*)&g_k[(size_t)(nbase + r) * EE + g * DD + tcol] = o;
            }
        }
    }
}

// ---------------------------------------------------------------------------
// Launch
// ---------------------------------------------------------------------------
extern "C" void kernel_launch(void* const* d_in, const int* in_sizes, int n_in,
                              void* d_out, int out_size)
{
    const float* x     = (const float*)d_in[0];
    const float* pos   = (const float*)d_in[1];
    const int*   batch = (const int*)d_in[2];
    const float* Wq    = (const float*)d_in[3];
    const float* bq    = (const float*)d_in[4];
    const float* Wv    = (const float*)d_in[5];
    const float* bv    = (const float*)d_in[6];
    const float* Wo    = (const float*)d_in[7];
    const float* bo    = (const float*)d_in[8];
    const float* freqs = (const float*)d_in[9];
    float* out = (float*)d_out;

    float *gq, *gk, *gv;
    cudaGetSymbolAddress((void**)&gq, g_q);
    cudaGetSymbolAddress((void**)&gk, g_k);
    cudaGetSymbolAddress((void**)&gv, g_v);

    dim3 gemmGrid(EE / BN, NN / BM);   // (3, 256)

    // 1) q_raw = x @ Wq + bq ; v = x @ Wv + bv
    sgemm_bias<<<gemmGrid, 256>>>(x, Wq, bq, gq, NN, CCH, EE);
    sgemm_bias<<<gemmGrid, 256>>>(x, Wv, bv, gv, NN, CCH, EE);

    // 2) RoPE (q in place, k = rope(ones))
    rope_kernel<<<(NN * GG + 255) / 256, 256>>>(pos, freqs);

    // 3) segment offsets
    offsets_kernel<<<1, 128>>>(batch, NN);

    // 4) kv = segsum(k outer v) / 512
    kv_kernel<<<dim3(GG, NGRAPH), 256>>>();

    // 5) attn = q . kv[batch]   (written into g_k)
    attn_kernel<<<dim3(16, NGRAPH), 256>>>();

    // 6) out = attn @ Wo + bo
    sgemm_bias<<<gemmGrid, 256>>>(gk, Wo, bo, out, NN, EE, CCH);
}

// round 3
// speedup vs baseline: 1.7326x; 1.7326x over previous
#include <cuda_runtime.h>
#include <cuda_bf16.h>
#include <cstdint>
#include <cstddef>

// Problem constants
#define NN 32768
#define CCH 384
#define EE 384
#define GG 12
#define DD 32
#define PPAIR 16
#define NGRAPH 64
#define NQV 768

#define SW128(off) ((off) ^ (((off) >> 3) & 0x70))

// ---------------------------------------------------------------------------
// Scratch
// ---------------------------------------------------------------------------
__device__ float g_q[(size_t)NN * EE];
__device__ float g_v[(size_t)NN * EE];
__device__ float g_k[(size_t)NN * EE];
__device__ float g_kv[(size_t)NGRAPH * GG * DD * DD];
__device__ int   g_off[NGRAPH + 1];
__device__ __nv_bfloat16 g_xh[(size_t)NN * CCH];
__device__ __nv_bfloat16 g_xl[(size_t)NN * CCH];
__device__ __nv_bfloat16 g_ah[(size_t)NN * EE];
__device__ __nv_bfloat16 g_al[(size_t)NN * EE];
__device__ __nv_bfloat16 g_wqvh[(size_t)NQV * CCH];
__device__ __nv_bfloat16 g_wqvl[(size_t)NQV * CCH];
__device__ __nv_bfloat16 g_woh[(size_t)CCH * EE];
__device__ __nv_bfloat16 g_wol[(size_t)CCH * EE];
__device__ float g_bqv[NQV];

// ---------------------------------------------------------------------------
// Small PTX wrappers (all sm_80-baseline; no tcgen05)
// ---------------------------------------------------------------------------
__device__ __forceinline__ uint32_t smem_u32(const void* p) {
    uint32_t a;
    asm("{ .reg .u64 t; cvta.to.shared.u64 t, %1; cvt.u32.u64 %0, t; }"
        : "=r"(a) : "l"(p));
    return a;
}
__device__ __forceinline__ void cp_async16(uint32_t dst, const void* src) {
    asm volatile("cp.async.cg.shared.global [%0], [%1], 16;"
                 :: "r"(dst), "l"(src));
}
__device__ __forceinline__ void cp_commit_wait0() {
    asm volatile("cp.async.commit_group;");
    asm volatile("cp.async.wait_group 0;");
}
__device__ __forceinline__ void ldm4(uint32_t* r, uint32_t addr) {
    asm volatile("ldmatrix.sync.aligned.m8n8.x4.shared.b16 {%0,%1,%2,%3}, [%4];"
                 : "=r"(r[0]), "=r"(r[1]), "=r"(r[2]), "=r"(r[3]) : "r"(addr));
}
__device__ __forceinline__ void mma_bf16(float* c, const uint32_t* a,
                                         const uint32_t b0, const uint32_t b1) {
    asm volatile(
        "mma.sync.aligned.m16n8k16.row.col.f32.bf16.bf16.f32 "
        "{%0,%1,%2,%3}, {%4,%5,%6,%7}, {%8,%9}, {%0,%1,%2,%3};"
        : "+f"(c[0]), "+f"(c[1]), "+f"(c[2]), "+f"(c[3])
        : "r"(a[0]), "r"(a[1]), "r"(a[2]), "r"(a[3]), "r"(b0), "r"(b1));
}

// ---------------------------------------------------------------------------
// bf16x2 tensor-core GEMM: C[128x128 tile] = A[M,384] @ B^T + bias
// A: [M,384] bf16 (hi/lo), B: [Ntot,384] bf16 (hi/lo, pre-transposed weights)
// D += Ah*Bh + Al*Bh + Ah*Bl  (fp32 accum)
// 256 threads = 8 warps (4x2), warp tile 32x64. BK=64. SW128 smem, ldmatrix.
// ---------------------------------------------------------------------------
__global__ __launch_bounds__(256, 2) void gemm_mma(
    const __nv_bfloat16* __restrict__ Ah, const __nv_bfloat16* __restrict__ Al,
    const __nv_bfloat16* __restrict__ Bh, const __nv_bfloat16* __restrict__ Bl,
    const float* __restrict__ bias, float* __restrict__ outQ,
    float* __restrict__ outV, int kTot)
{
    extern __shared__ char smem[];
    char* sAh = smem;
    char* sAl = smem + 16384;
    char* sBh = smem + 32768;
    char* sBl = smem + 49152;
    const uint32_t uAh = smem_u32(sAh);
    const uint32_t uAl = smem_u32(sAl);
    const uint32_t uBh = smem_u32(sBh);
    const uint32_t uBl = smem_u32(sBl);

    const int tid = threadIdx.x;
    const int bm = blockIdx.y * 128;
    const int bn = blockIdx.x * 128;

    // loader mapping: row = tid>>1 (0..127), 4 chunks of 16B at (tid&1)*4..+3
    const int lrow = tid >> 1;
    const int lc0 = (tid & 1) * 4;
    const char* gA_h = (const char*)(Ah + (size_t)(bm + lrow) * kTot);
    const char* gA_l = (const char*)(Al + (size_t)(bm + lrow) * kTot);
    const char* gB_h = (const char*)(Bh + (size_t)(bn + lrow) * kTot);
    const char* gB_l = (const char*)(Bl + (size_t)(bn + lrow) * kTot);
    uint32_t sw[4];
#pragma unroll
    for (int i = 0; i < 4; i++)
        sw[i] = SW128((uint32_t)lrow * 128 + (lc0 + i) * 16);

    const int wid = tid >> 5, lane = tid & 31;
    const int wm = (wid & 3) * 32;    // warp M offset
    const int wn = (wid >> 2) * 64;   // warp N offset

    // ldmatrix lane address components (pre-swizzle byte offsets)
    // A (x4 over m16k16): row = wm + mt*16 + (lane&15); byte = kb + (lane>>4)*16
    const uint32_t aRowOff = (uint32_t)(wm + (lane & 15)) * 128;
    const uint32_t aByte = (uint32_t)(lane >> 4) * 16;
    // B (x4 over two n8k16): row = wn + nt2*16 + (lane>>4)*8 + (lane&7)
    //                        byte = kb + ((lane>>3)&1)*16
    const uint32_t bRowOff =
        (uint32_t)(wn + ((lane >> 4) << 3) + (lane & 7)) * 128;
    const uint32_t bByte = (uint32_t)((lane >> 3) & 1) * 16;

    float acc[2][8][4];
#pragma unroll
    for (int mt = 0; mt < 2; mt++)
#pragma unroll
        for (int nt = 0; nt < 8; nt++)
#pragma unroll
            for (int j = 0; j < 4; j++) acc[mt][nt][j] = 0.f;

    const int nIter = kTot / 64;
    for (int c = 0; c < nIter; c++) {
        const int k0b = c * 128;   // byte offset within a 2-byte-elem row
        __syncthreads();
#pragma unroll
        for (int i = 0; i < 4; i++) {
            const int go = k0b + (lc0 + i) * 16;
            cp_async16(uAh + sw[i], gA_h + go);
            cp_async16(uAl + sw[i], gA_l + go);
            cp_async16(uBh + sw[i], gB_h + go);
            cp_async16(uBl + sw[i], gB_l + go);
        }
        cp_commit_wait0();
        __syncthreads();

#pragma unroll
        for (int ks = 0; ks < 4; ks++) {
            const uint32_t kb = (uint32_t)ks * 32;
            uint32_t ax[2][4], bx[4][4];
            // Ah frags
#pragma unroll
            for (int mt = 0; mt < 2; mt++)
                ldm4(ax[mt], uAh + SW128(aRowOff + mt * 2048 + kb + aByte));
            // Bh frags
#pragma unroll
            for (int nt2 = 0; nt2 < 4; nt2++)
                ldm4(bx[nt2], uBh + SW128(bRowOff + nt2 * 2048 + kb + bByte));
            // Ah * Bh
#pragma unroll
            for (int mt = 0; mt < 2; mt++)
#pragma unroll
                for (int nt = 0; nt < 8; nt++)
                    mma_bf16(acc[mt][nt], ax[mt],
                             bx[nt >> 1][(nt & 1) * 2], bx[nt >> 1][(nt & 1) * 2 + 1]);
            // Al frags -> reuse a regs after? need Ah later for Bl; use sep regs
            uint32_t alx[2][4];
#pragma unroll
            for (int mt = 0; mt < 2; mt++)
                ldm4(alx[mt], uAl + SW128(aRowOff + mt * 2048 + kb + aByte));
            // Al * Bh
#pragma unroll
            for (int mt = 0; mt < 2; mt++)
#pragma unroll
                for (int nt = 0; nt < 8; nt++)
                    mma_bf16(acc[mt][nt], alx[mt],
                             bx[nt >> 1][(nt & 1) * 2], bx[nt >> 1][(nt & 1) * 2 + 1]);
            // Bl frags (overwrite bx)
#pragma unroll
            for (int nt2 = 0; nt2 < 4; nt2++)
                ldm4(bx[nt2], uBl + SW128(bRowOff + nt2 * 2048 + kb + bByte));
            // Ah * Bl
#pragma unroll
            for (int mt = 0; mt < 2; mt++)
#pragma unroll
                for (int nt = 0; nt < 8; nt++)
                    mma_bf16(acc[mt][nt], ax[mt],
                             bx[nt >> 1][(nt & 1) * 2], bx[nt >> 1][(nt & 1) * 2 + 1]);
        }
    }

    // Epilogue: direct float2 stores (+bias)
    float* dst = (bn < EE) ? outQ : outV;
    const int bcol = (bn < EE) ? bn : bn - EE;
    const int r0 = bm + wm + (lane >> 2);
    const int cb = wn + (lane & 3) * 2;
#pragma unroll
    for (int mt = 0; mt < 2; mt++) {
        const int row = r0 + mt * 16;
#pragma unroll
        for (int nt = 0; nt < 8; nt++) {
            const int col = cb + nt * 8;
            const float b0 = bias[bn + col];
            const float b1 = bias[bn + col + 1];
            float2 v0, v1;
            v0.x = acc[mt][nt][0] + b0; v0.y = acc[mt][nt][1] + b1;
            v1.x = acc[mt][nt][2] + b0; v1.y = acc[mt][nt][3] + b1;
            *(float2*)&dst[(size_t)row * EE + bcol + col]       = v0;
            *(float2*)&dst[(size_t)(row + 8) * EE + bcol + col] = v1;
        }
    }
}

// ---------------------------------------------------------------------------
// x -> bf16 hi/lo split
// ---------------------------------------------------------------------------
__global__ void convert_x_kernel(const float* __restrict__ x)
{
    int i = (blockIdx.x * blockDim.x + threadIdx.x) * 4;
    if (i >= NN * CCH) return;
    float4 v = *(const float4*)(x + i);
    float vv[4] = {v.x, v.y, v.z, v.w};
    __nv_bfloat16 h[4], l[4];
#pragma unroll
    for (int j = 0; j < 4; j++) {
        h[j] = __float2bfloat16(vv[j]);
        l[j] = __float2bfloat16(vv[j] - __bfloat162float(h[j]));
    }
    __nv_bfloat162 h01; h01.x = h[0]; h01.y = h[1];
    __nv_bfloat162 h23; h23.x = h[2]; h23.y = h[3];
    __nv_bfloat162 l01; l01.x = l[0]; l01.y = l[1];
    __nv_bfloat162 l23; l23.x = l[2]; l23.y = l[3];
    *(__nv_bfloat162*)(g_xh + i)     = h01;
    *(__nv_bfloat162*)(g_xh + i + 2) = h23;
    *(__nv_bfloat162*)(g_xl + i)     = l01;
    *(__nv_bfloat162*)(g_xl + i + 2) = l23;
}

// ---------------------------------------------------------------------------
// Transpose + split weights: WqT|WvT packed [768][384], WoT [384][384], bias
// ---------------------------------------------------------------------------
__global__ void prep_w_kernel(const float* __restrict__ Wq,
                              const float* __restrict__ Wv,
                              const float* __restrict__ Wo,
                              const float* __restrict__ bq,
                              const float* __restrict__ bv)
{
    int idx = blockIdx.x * blockDim.x + threadIdx.x;
    const int T1 = NQV * CCH;
    if (idx < T1) {
        int n = idx / CCH, k = idx % CCH;
        float f = (n < EE) ? Wq[(size_t)k * EE + n] : Wv[(size_t)k * EE + (n - EE)];
        __nv_bfloat16 h = __float2bfloat16(f);
        g_wqvh[idx] = h;
        g_wqvl[idx] = __float2bfloat16(f - __bfloat162float(h));
    } else if (idx < T1 + CCH * EE) {
        int j = idx - T1;
        int n = j / EE, k = j % EE;   // n = C (output col of Wo), k = E
        float f = Wo[(size_t)k * CCH + n];
        __nv_bfloat16 h = __float2bfloat16(f);
        g_woh[j] = h;
        g_wol[j] = __float2bfloat16(f - __bfloat162float(h));
    }
    if (idx < NQV) g_bqv[idx] = (idx < EE) ? bq[idx] : bv[idx - EE];
}

// ---------------------------------------------------------------------------
// RoPE: q in-place, k = rope(ones)
// ---------------------------------------------------------------------------
__global__ void rope_kernel(const float* __restrict__ pos,
                            const float* __restrict__ freqs)
{
    int idx = blockIdx.x * blockDim.x + threadIdx.x;
    if (idx >= NN * GG) return;
    int n = idx / GG;
    int g = idx % GG;

    float px = pos[n * 3 + 0];
    float py = pos[n * 3 + 1];
    float pz = pos[n * 3 + 2];

    size_t base = (size_t)n * EE + g * DD;
    float qv[DD], qo[DD], ko[DD];
    const float4* qp = (const float4*)(g_q + base);
#pragma unroll
    for (int i = 0; i < DD / 4; i++) ((float4*)qv)[i] = qp[i];

#pragma unroll
    for (int p = 0; p < PPAIR; p++) {
        const float* f = freqs + ((size_t)g * PPAIR + p) * 3;
        float ph = px * f[0] + py * f[1] + pz * f[2];
        float c = __cosf(ph);
        float s = __sinf(ph);
        float x1 = qv[2 * p], x2 = qv[2 * p + 1];
        qo[2 * p]     = x1 * c - x2 * s;
        qo[2 * p + 1] = x1 * s + x2 * c;
        ko[2 * p]     = c - s;
        ko[2 * p + 1] = s + c;
    }
    float4* qw = (float4*)(g_q + base);
    float4* kw = (float4*)(g_k + base);
#pragma unroll
    for (int i = 0; i < DD / 4; i++) {
        qw[i] = ((float4*)qo)[i];
        kw[i] = ((float4*)ko)[i];
    }
}

// ---------------------------------------------------------------------------
// Segment offsets
// ---------------------------------------------------------------------------
__global__ void offsets_kernel(const int* __restrict__ batch, int n)
{
    int t = threadIdx.x;
    if (t > NGRAPH) return;
    if (t == NGRAPH) { g_off[NGRAPH] = n; return; }
    int lo = 0, hi = n;
    while (lo < hi) {
        int mid = (lo + hi) >> 1;
        if (batch[mid] < t) lo = mid + 1; else hi = mid;
    }
    g_off[t] = lo;
}

// ---------------------------------------------------------------------------
// KV segment reduction
// ---------------------------------------------------------------------------
#define KVCH 8
__global__ __launch_bounds__(256) void kv_kernel()
{
    int gi = blockIdx.x;
    int b  = blockIdx.y;
    int s = g_off[b], e = g_off[b + 1];
    int tid = threadIdx.x;

    __shared__ float sk[KVCH][DD];
    __shared__ float sv[KVCH][DD];

    float a0 = 0.f, a1 = 0.f, a2 = 0.f, a3 = 0.f;
    int d  = tid >> 3;
    int e0 = (tid & 7) << 2;

    for (int n0 = s; n0 < e; n0 += KVCH) {
        int cnt = min(KVCH, e - n0);
        __syncthreads();
        for (int i = tid; i < cnt * DD; i += 256) {
            int nn = i >> 5, dd = i & 31;
            size_t off = (size_t)(n0 + nn) * EE + gi * DD + dd;
            sk[nn][dd] = g_k[off];
            sv[nn][dd] = g_v[off];
        }
        __syncthreads();
        for (int c = 0; c < cnt; c++) {
            float kd = sk[c][d];
            a0 += kd * sv[c][e0 + 0];
            a1 += kd * sv[c][e0 + 1];
            a2 += kd * sv[c][e0 + 2];
            a3 += kd * sv[c][e0 + 3];
        }
    }
    const float inv = 1.0f / 512.0f;
    float* dst = g_kv + (((size_t)b * GG + gi) * DD + d) * DD + e0;
    dst[0] = a0 * inv; dst[1] = a1 * inv; dst[2] = a2 * inv; dst[3] = a3 * inv;
}

// ---------------------------------------------------------------------------
// Apply: attn = q . kv[batch]; emits bf16 hi/lo for the final GEMM
// ---------------------------------------------------------------------------
#define ACH 128
__global__ __launch_bounds__(256) void attn_kernel()
{
    int c = blockIdx.x;
    int b = blockIdx.y;
    int s = g_off[b], e = g_off[b + 1];
    int nbase = s + c * ACH;
    if (nbase >= e) return;
    int cnt = min(ACH, e - nbase);
    int tid = threadIdx.x;

    __shared__ float Qs[DD][ACH + 4];
    __shared__ float Ks[DD][DD];

    int trow = (tid >> 3) * 4;
    int tcol = (tid & 7) * 4;

    for (int g = 0; g < GG; g++) {
        __syncthreads();
        for (int i = tid; i < ACH * DD; i += 256) {
            int nn = i >> 5, kk = i & 31;
            Qs[kk][nn] = (nn < cnt)
                ? g_q[(size_t)(nbase + nn) * EE + g * DD + kk] : 0.f;
        }
        {
            const float* kvp = g_kv + ((size_t)b * GG + g) * DD * DD;
            for (int i = tid; i < DD * DD; i += 256)
                (&Ks[0][0])[i] = kvp[i];
        }
        __syncthreads();

        float acc[4][4];
#pragma unroll
        for (int i = 0; i < 4; i++)
#pragma unroll
            for (int j = 0; j < 4; j++) acc[i][j] = 0.f;

#pragma unroll
        for (int k = 0; k < DD; k++) {
            float ra[4], rb[4];
            *(float4*)ra = *(const float4*)&Qs[k][trow];
            *(float4*)rb = *(const float4*)&Ks[k][tcol];
#pragma unroll
            for (int i = 0; i < 4; i++)
#pragma unroll
                for (int j = 0; j < 4; j++)
                    acc[i][j] += ra[i] * rb[j];
        }

#pragma unroll
        for (int i = 0; i < 4; i++) {
            int r = trow + i;
            if (r < cnt) {
                size_t off = (size_t)(nbase + r) * EE + g * DD + tcol;
                __nv_bfloat16 h[4], l[4];
#pragma unroll
                for (int j = 0; j < 4; j++) {
                    h[j] = __float2bfloat16(acc[i][j]);
                    l[j] = __float2bfloat16(acc[i][j] - __bfloat162float(h[j]));
                }
                __nv_bfloat162 h01; h01.x = h[0]; h01.y = h[1];
                __nv_bfloat162 h23; h23.x = h[2]; h23.y = h[3];
                __nv_bfloat162 l01; l01.x = l[0]; l01.y = l[1];
                __nv_bfloat162 l23; l23.x = l[2]; l23.y = l[3];
                *(__nv_bfloat162*)(g_ah + off)     = h01;
                *(__nv_bfloat162*)(g_ah + off + 2) = h23;
                *(__nv_bfloat162*)(g_al + off)     = l01;
                *(__nv_bfloat162*)(g_al + off + 2) = l23;
            }
        }
    }
}

// ---------------------------------------------------------------------------
// Launch
// ---------------------------------------------------------------------------
#define GEMM_SMEM 65536

extern "C" void kernel_launch(void* const* d_in, const int* in_sizes, int n_in,
                              void* d_out, int out_size)
{
    const float* x     = (const float*)d_in[0];
    const float* pos   = (const float*)d_in[1];
    const int*   batch = (const int*)d_in[2];
    const float* Wq    = (const float*)d_in[3];
    const float* bq    = (const float*)d_in[4];
    const float* Wv    = (const float*)d_in[5];
    const float* bv    = (const float*)d_in[6];
    const float* Wo    = (const float*)d_in[7];
    const float* bo    = (const float*)d_in[8];
    const float* freqs = (const float*)d_in[9];
    float* out = (float*)d_out;

    float *gq, *gv, *gbqv;
    __nv_bfloat16 *gxh, *gxl, *gah, *gal, *gwqvh, *gwqvl, *gwoh, *gwol;
    cudaGetSymbolAddress((void**)&gq, g_q);
    cudaGetSymbolAddress((void**)&gv, g_v);
    cudaGetSymbolAddress((void**)&gbqv, g_bqv);
    cudaGetSymbolAddress((void**)&gxh, g_xh);
    cudaGetSymbolAddress((void**)&gxl, g_xl);
    cudaGetSymbolAddress((void**)&gah, g_ah);
    cudaGetSymbolAddress((void**)&gal, g_al);
    cudaGetSymbolAddress((void**)&gwqvh, g_wqvh);
    cudaGetSymbolAddress((void**)&gwqvl, g_wqvl);
    cudaGetSymbolAddress((void**)&gwoh, g_woh);
    cudaGetSymbolAddress((void**)&gwol, g_wol);

    cudaFuncSetAttribute(gemm_mma,
                         cudaFuncAttributeMaxDynamicSharedMemorySize, GEMM_SMEM);

    // 1) bf16 hi/lo conversion of x; weight transpose+split (+bias pack)
    convert_x_kernel<<<(NN * CCH / 4 + 255) / 256, 256>>>(x);
    prep_w_kernel<<<(NQV * CCH + CCH * EE + 255) / 256, 256>>>(Wq, Wv, Wo, bq, bv);

    // 2) fused Q|V projection: [32768,384] @ [384,768]^T -> g_q, g_v
    gemm_mma<<<dim3(NQV / 128, NN / 128), 256, GEMM_SMEM>>>(
        gxh, gxl, gwqvh, gwqvl, gbqv, gq, gv, CCH);

    // 3) RoPE
    rope_kernel<<<(NN * GG + 255) / 256, 256>>>(pos, freqs);

    // 4) segment offsets
    offsets_kernel<<<1, 128>>>(batch, NN);

    // 5) kv = segsum(k outer v) / 512
    kv_kernel<<<dim3(GG, NGRAPH), 256>>>();

    // 6) attn = q . kv[batch] -> bf16 hi/lo
    attn_kernel<<<dim3(16, NGRAPH), 256>>>();

    // 7) out = attn @ Wo + bo
    gemm_mma<<<dim3(EE / 128, NN / 128), 256, GEMM_SMEM>>>(
        gah, gal, gwoh, gwol, bo, out, out, EE);
}

// round 4
// speedup vs baseline: 1.7651x; 1.0188x over previous
#include <cuda_runtime.h>
#include <cuda_bf16.h>
#include <cstdint>
#include <cstddef>

// Problem constants
#define NN 32768
#define CCH 384
#define EE 384
#define GG 12
#define DD 32
#define PPAIR 16
#define NGRAPH 64
#define NQV 768

#define SW128(off) ((off) ^ (((off) >> 3) & 0x70))

// ---------------------------------------------------------------------------
// Scratch
// ---------------------------------------------------------------------------
__device__ float g_q[(size_t)NN * EE];
__device__ float g_v[(size_t)NN * EE];
__device__ float g_k[(size_t)NN * EE];
__device__ float g_kv[(size_t)NGRAPH * GG * DD * DD];
__device__ __nv_bfloat16 g_xh[(size_t)NN * CCH];
__device__ __nv_bfloat16 g_xl[(size_t)NN * CCH];
__device__ __nv_bfloat16 g_ah[(size_t)NN * EE];
__device__ __nv_bfloat16 g_al[(size_t)NN * EE];
__device__ __nv_bfloat16 g_wqvh[(size_t)NQV * CCH];
__device__ __nv_bfloat16 g_wqvl[(size_t)NQV * CCH];
__device__ __nv_bfloat16 g_woh[(size_t)CCH * EE];
__device__ __nv_bfloat16 g_wol[(size_t)CCH * EE];
__device__ float g_bqv[NQV];

// ---------------------------------------------------------------------------
// PTX wrappers (sm_80-baseline only)
// ---------------------------------------------------------------------------
__device__ __forceinline__ uint32_t smem_u32(const void* p) {
    uint32_t a;
    asm("{ .reg .u64 t; cvta.to.shared.u64 t, %1; cvt.u32.u64 %0, t; }"
        : "=r"(a) : "l"(p));
    return a;
}
__device__ __forceinline__ void cp_async16(uint32_t dst, const void* src) {
    asm volatile("cp.async.cg.shared.global [%0], [%1], 16;"
                 :: "r"(dst), "l"(src));
}
__device__ __forceinline__ void cp_commit() {
    asm volatile("cp.async.commit_group;");
}
__device__ __forceinline__ void cp_wait1() {
    asm volatile("cp.async.wait_group 1;");
}
__device__ __forceinline__ void cp_wait0() {
    asm volatile("cp.async.wait_group 0;");
}
__device__ __forceinline__ void ldm4(uint32_t* r, uint32_t addr) {
    asm volatile("ldmatrix.sync.aligned.m8n8.x4.shared.b16 {%0,%1,%2,%3}, [%4];"
                 : "=r"(r[0]), "=r"(r[1]), "=r"(r[2]), "=r"(r[3]) : "r"(addr));
}
__device__ __forceinline__ void mma_bf16(float* c, const uint32_t* a,
                                         const uint32_t b0, const uint32_t b1) {
    asm volatile(
        "mma.sync.aligned.m16n8k16.row.col.f32.bf16.bf16.f32 "
        "{%0,%1,%2,%3}, {%4,%5,%6,%7}, {%8,%9}, {%0,%1,%2,%3};"
        : "+f"(c[0]), "+f"(c[1]), "+f"(c[2]), "+f"(c[3])
        : "r"(a[0]), "r"(a[1]), "r"(a[2]), "r"(a[3]), "r"(b0), "r"(b1));
}

// ---------------------------------------------------------------------------
// Pipelined bf16x2 tensor GEMM, 128x128 tile, BK=64, 2-stage cp.async.
// D = Ah*Bh + Al*Bh + Ah*Bl (fp32 accum). mode 1 = QV projection (RoPE fused
// into epilogue for the Q half, writes q_rot + k_rot; V half plain).
// mode 0 = plain store (final Wo GEMM).
// ---------------------------------------------------------------------------
#define STAGE_BYTES 65536
#define GEMM_SMEM (2 * STAGE_BYTES)

__global__ __launch_bounds__(256, 1) void gemm_mma(
    const __nv_bfloat16* __restrict__ Ah, const __nv_bfloat16* __restrict__ Al,
    const __nv_bfloat16* __restrict__ Bh, const __nv_bfloat16* __restrict__ Bl,
    const float* __restrict__ bias, float* __restrict__ outQ,
    float* __restrict__ outV, float* __restrict__ outK,
    const float* __restrict__ pos, const float* __restrict__ freqs,
    int kTot, int mode)
{
    extern __shared__ char smem[];
    const uint32_t uS = smem_u32(smem);

    const int tid = threadIdx.x;
    const int bm = blockIdx.y * 128;
    const int bn = blockIdx.x * 128;

    // loader: row = tid>>1, two threads cover the 128B row (4 x 16B each)
    const int lrow = tid >> 1;
    const int lc0 = (tid & 1) * 4;
    const char* gA_h = (const char*)(Ah + (size_t)(bm + lrow) * kTot);
    const char* gA_l = (const char*)(Al + (size_t)(bm + lrow) * kTot);
    const char* gB_h = (const char*)(Bh + (size_t)(bn + lrow) * kTot);
    const char* gB_l = (const char*)(Bl + (size_t)(bn + lrow) * kTot);
    uint32_t sw[4];
#pragma unroll
    for (int i = 0; i < 4; i++)
        sw[i] = SW128((uint32_t)lrow * 128 + (lc0 + i) * 16);

    const int wid = tid >> 5, lane = tid & 31;
    const int wm = (wid & 3) * 32;
    const int wn = (wid >> 2) * 64;

    const uint32_t aRowOff = (uint32_t)(wm + (lane & 15)) * 128;
    const uint32_t aByte = (uint32_t)(lane >> 4) * 16;
    const uint32_t bRowOff =
        (uint32_t)(wn + ((lane >> 4) << 3) + (lane & 7)) * 128;
    const uint32_t bByte = (uint32_t)((lane >> 3) & 1) * 16;

    float acc[2][8][4];
#pragma unroll
    for (int mt = 0; mt < 2; mt++)
#pragma unroll
        for (int nt = 0; nt < 8; nt++)
#pragma unroll
            for (int j = 0; j < 4; j++) acc[mt][nt][j] = 0.f;

    const int nIter = kTot / 64;

    // prologue: stage 0
    {
#pragma unroll
        for (int i = 0; i < 4; i++) {
            const int go = (lc0 + i) * 16;
            cp_async16(uS + sw[i], gA_h + go);
            cp_async16(uS + 16384 + sw[i], gA_l + go);
            cp_async16(uS + 32768 + sw[i], gB_h + go);
            cp_async16(uS + 49152 + sw[i], gB_l + go);
        }
        cp_commit();
    }

    for (int c = 0; c < nIter; c++) {
        if (c + 1 < nIter) {
            const uint32_t sb = uS + ((c + 1) & 1) * STAGE_BYTES;
            const int k0b = (c + 1) * 128;
#pragma unroll
            for (int i = 0; i < 4; i++) {
                const int go = k0b + (lc0 + i) * 16;
                cp_async16(sb + sw[i], gA_h + go);
                cp_async16(sb + 16384 + sw[i], gA_l + go);
                cp_async16(sb + 32768 + sw[i], gB_h + go);
                cp_async16(sb + 49152 + sw[i], gB_l + go);
            }
            cp_commit();
            cp_wait1();
        } else {
            cp_wait0();
        }
        __syncthreads();

        const uint32_t st = uS + (c & 1) * STAGE_BYTES;
        const uint32_t uAh = st, uAl = st + 16384;
        const uint32_t uBh = st + 32768, uBl = st + 49152;

#pragma unroll
        for (int ks = 0; ks < 4; ks++) {
            const uint32_t kb = (uint32_t)ks * 32;
            uint32_t ax[2][4], alx[2][4], bx[4][4];
#pragma unroll
            for (int mt = 0; mt < 2; mt++)
                ldm4(ax[mt], uAh + SW128(aRowOff + mt * 2048 + kb + aByte));
#pragma unroll
            for (int nt2 = 0; nt2 < 4; nt2++)
                ldm4(bx[nt2], uBh + SW128(bRowOff + nt2 * 2048 + kb + bByte));
#pragma unroll
            for (int mt = 0; mt < 2; mt++)
#pragma unroll
                for (int nt = 0; nt < 8; nt++)
                    mma_bf16(acc[mt][nt], ax[mt],
                             bx[nt >> 1][(nt & 1) * 2], bx[nt >> 1][(nt & 1) * 2 + 1]);
#pragma unroll
            for (int mt = 0; mt < 2; mt++)
                ldm4(alx[mt], uAl + SW128(aRowOff + mt * 2048 + kb + aByte));
#pragma unroll
            for (int mt = 0; mt < 2; mt++)
#pragma unroll
                for (int nt = 0; nt < 8; nt++)
                    mma_bf16(acc[mt][nt], alx[mt],
                             bx[nt >> 1][(nt & 1) * 2], bx[nt >> 1][(nt & 1) * 2 + 1]);
#pragma unroll
            for (int nt2 = 0; nt2 < 4; nt2++)
                ldm4(bx[nt2], uBl + SW128(bRowOff + nt2 * 2048 + kb + bByte));
#pragma unroll
            for (int mt = 0; mt < 2; mt++)
#pragma unroll
                for (int nt = 0; nt < 8; nt++)
                    mma_bf16(acc[mt][nt], ax[mt],
                             bx[nt >> 1][(nt & 1) * 2], bx[nt >> 1][(nt & 1) * 2 + 1]);
        }
        __syncthreads();
    }

    // ------------------------- epilogue -------------------------
    const int r0 = bm + wm + (lane >> 2);
    const int cb = wn + (lane & 3) * 2;

    if (mode == 1 && bn < EE) {
        // Q half: add bias, apply RoPE, write q_rot and k_rot.
        // acc[mt][nt][{0,1}] -> row r0+mt*16,     cols (cb+nt*8, +1)
        // acc[mt][nt][{2,3}] -> row r0+mt*16+8,   same cols
        float px[4], py[4], pz[4];
        int rr[4];
#pragma unroll
        for (int j = 0; j < 4; j++) {
            rr[j] = r0 + (j >> 1) * 16 + (j & 1) * 8;
            px[j] = pos[rr[j] * 3 + 0];
            py[j] = pos[rr[j] * 3 + 1];
            pz[j] = pos[rr[j] * 3 + 2];
        }
#pragma unroll
        for (int nt = 0; nt < 8; nt++) {
            const int gc = bn + cb + nt * 8;          // even global column
            const int g = gc >> 5;
            const int p = (gc & 31) >> 1;
            const float* f = freqs + ((size_t)g * PPAIR + p) * 3;
            const float fx = f[0], fy = f[1], fz = f[2];
            const float b0 = bias[gc], b1 = bias[gc + 1];
#pragma unroll
            for (int mt = 0; mt < 2; mt++) {
#pragma unroll
                for (int h = 0; h < 2; h++) {
                    const int j = mt * 2 + h;
                    const float ph = px[j] * fx + py[j] * fy + pz[j] * fz;
                    const float sn = __sinf(ph);
                    const float cs = __cosf(ph);
                    const float x1 = acc[mt][nt][h * 2 + 0] + b0;
                    const float x2 = acc[mt][nt][h * 2 + 1] + b1;
                    float2 qv, kv;
                    qv.x = x1 * cs - x2 * sn;
                    qv.y = x1 * sn + x2 * cs;
                    kv.x = cs - sn;
                    kv.y = sn + cs;
                    const size_t o = (size_t)rr[j] * EE + gc;
                    *(float2*)&outQ[o] = qv;
                    *(float2*)&outK[o] = kv;
                }
            }
        }
    } else {
        float* dst = (mode == 1) ? outV : outQ;
        const int bcol = (mode == 1) ? bn - EE : bn;
#pragma unroll
        for (int mt = 0; mt < 2; mt++) {
            const int row = r0 + mt * 16;
#pragma unroll
            for (int nt = 0; nt < 8; nt++) {
                const int col = cb + nt * 8;
                const float b0 = bias[bn + col];
                const float b1 = bias[bn + col + 1];
                float2 v0, v1;
                v0.x = acc[mt][nt][0] + b0; v0.y = acc[mt][nt][1] + b1;
                v1.x = acc[mt][nt][2] + b0; v1.y = acc[mt][nt][3] + b1;
                *(float2*)&dst[(size_t)row * EE + bcol + col]       = v0;
                *(float2*)&dst[(size_t)(row + 8) * EE + bcol + col] = v1;
            }
        }
    }
}

// ---------------------------------------------------------------------------
// x -> bf16 hi/lo split
// ---------------------------------------------------------------------------
__global__ void convert_x_kernel(const float* __restrict__ x)
{
    int i = (blockIdx.x * blockDim.x + threadIdx.x) * 4;
    if (i >= NN * CCH) return;
    float4 v = *(const float4*)(x + i);
    float vv[4] = {v.x, v.y, v.z, v.w};
    __nv_bfloat16 h[4], l[4];
#pragma unroll
    for (int j = 0; j < 4; j++) {
        h[j] = __float2bfloat16(vv[j]);
        l[j] = __float2bfloat16(vv[j] - __bfloat162float(h[j]));
    }
    __nv_bfloat162 h01; h01.x = h[0]; h01.y = h[1];
    __nv_bfloat162 h23; h23.x = h[2]; h23.y = h[3];
    __nv_bfloat162 l01; l01.x = l[0]; l01.y = l[1];
    __nv_bfloat162 l23; l23.x = l[2]; l23.y = l[3];
    *(__nv_bfloat162*)(g_xh + i)     = h01;
    *(__nv_bfloat162*)(g_xh + i + 2) = h23;
    *(__nv_bfloat162*)(g_xl + i)     = l01;
    *(__nv_bfloat162*)(g_xl + i + 2) = l23;
}

// ---------------------------------------------------------------------------
// Transpose + split weights
// ---------------------------------------------------------------------------
__global__ void prep_w_kernel(const float* __restrict__ Wq,
                              const float* __restrict__ Wv,
                              const float* __restrict__ Wo,
                              const float* __restrict__ bq,
                              const float* __restrict__ bv)
{
    int idx = blockIdx.x * blockDim.x + threadIdx.x;
    const int T1 = NQV * CCH;
    if (idx < T1) {
        int n = idx / CCH, k = idx % CCH;
        float f = (n < EE) ? Wq[(size_t)k * EE + n] : Wv[(size_t)k * EE + (n - EE)];
        __nv_bfloat16 h = __float2bfloat16(f);
        g_wqvh[idx] = h;
        g_wqvl[idx] = __float2bfloat16(f - __bfloat162float(h));
    } else if (idx < T1 + CCH * EE) {
        int j = idx - T1;
        int n = j / EE, k = j % EE;
        float f = Wo[(size_t)k * CCH + n];
        __nv_bfloat16 h = __float2bfloat16(f);
        g_woh[j] = h;
        g_wol[j] = __float2bfloat16(f - __bfloat162float(h));
    }
    if (idx < NQV) g_bqv[idx] = (idx < EE) ? bq[idx] : bv[idx - EE];
}

// ---------------------------------------------------------------------------
// Inline segment bound (batch is sorted)
// ---------------------------------------------------------------------------
__device__ __forceinline__ int seg_lower(const int* __restrict__ batch, int t)
{
    int lo = 0, hi = NN;
    while (lo < hi) {
        int mid = (lo + hi) >> 1;
        if (batch[mid] < t) lo = mid + 1; else hi = mid;
    }
    return lo;
}

// ---------------------------------------------------------------------------
// KV segment reduction
// ---------------------------------------------------------------------------
#define KVCH 8
__global__ __launch_bounds__(256) void kv_kernel(const int* __restrict__ batch)
{
    int gi = blockIdx.x;
    int b  = blockIdx.y;
    int s = seg_lower(batch, b);
    int e = seg_lower(batch, b + 1);
    int tid = threadIdx.x;

    __shared__ float sk[KVCH][DD];
    __shared__ float sv[KVCH][DD];

    float a0 = 0.f, a1 = 0.f, a2 = 0.f, a3 = 0.f;
    int d  = tid >> 3;
    int e0 = (tid & 7) << 2;

    for (int n0 = s; n0 < e; n0 += KVCH) {
        int cnt = min(KVCH, e - n0);
        __syncthreads();
        for (int i = tid; i < cnt * DD; i += 256) {
            int nn = i >> 5, dd = i & 31;
            size_t off = (size_t)(n0 + nn) * EE + gi * DD + dd;
            sk[nn][dd] = g_k[off];
            sv[nn][dd] = g_v[off];
        }
        __syncthreads();
        for (int c = 0; c < cnt; c++) {
            float kd = sk[c][d];
            a0 += kd * sv[c][e0 + 0];
            a1 += kd * sv[c][e0 + 1];
            a2 += kd * sv[c][e0 + 2];
            a3 += kd * sv[c][e0 + 3];
        }
    }
    const float inv = 1.0f / 512.0f;
    float* dst = g_kv + (((size_t)b * GG + gi) * DD + d) * DD + e0;
    dst[0] = a0 * inv; dst[1] = a1 * inv; dst[2] = a2 * inv; dst[3] = a3 * inv;
}

// ---------------------------------------------------------------------------
// Apply: attn = q . kv[batch]; emits bf16 hi/lo for the final GEMM
// ---------------------------------------------------------------------------
#define ACH 128
__global__ __launch_bounds__(256) void attn_kernel(const int* __restrict__ batch)
{
    int c = blockIdx.x;
    int b = blockIdx.y;
    int s = seg_lower(batch, b);
    int e = seg_lower(batch, b + 1);
    int nbase = s + c * ACH;
    if (nbase >= e) return;
    int cnt = min(ACH, e - nbase);
    int tid = threadIdx.x;

    __shared__ float Qs[DD][ACH + 4];
    __shared__ float Ks[DD][DD];

    int trow = (tid >> 3) * 4;
    int tcol = (tid & 7) * 4;

    for (int g = 0; g < GG; g++) {
        __syncthreads();
        for (int i = tid; i < ACH * DD; i += 256) {
            int nn = i >> 5, kk = i & 31;
            Qs[kk][nn] = (nn < cnt)
                ? g_q[(size_t)(nbase + nn) * EE + g * DD + kk] : 0.f;
        }
        {
            const float* kvp = g_kv + ((size_t)b * GG + g) * DD * DD;
            for (int i = tid; i < DD * DD; i += 256)
                (&Ks[0][0])[i] = kvp[i];
        }
        __syncthreads();

        float acc[4][4];
#pragma unroll
        for (int i = 0; i < 4; i++)
#pragma unroll
            for (int j = 0; j < 4; j++) acc[i][j] = 0.f;

#pragma unroll
        for (int k = 0; k < DD; k++) {
            float ra[4], rb[4];
            *(float4*)ra = *(const float4*)&Qs[k][trow];
            *(float4*)rb = *(const float4*)&Ks[k][tcol];
#pragma unroll
            for (int i = 0; i < 4; i++)
#pragma unroll
                for (int j = 0; j < 4; j++)
                    acc[i][j] += ra[i] * rb[j];
        }

#pragma unroll
        for (int i = 0; i < 4; i++) {
            int r = trow + i;
            if (r < cnt) {
                size_t off = (size_t)(nbase + r) * EE + g * DD + tcol;
                __nv_bfloat16 h[4], l[4];
#pragma unroll
                for (int j = 0; j < 4; j++) {
                    h[j] = __float2bfloat16(acc[i][j]);
                    l[j] = __float2bfloat16(acc[i][j] - __bfloat162float(h[j]));
                }
                __nv_bfloat162 h01; h01.x = h[0]; h01.y = h[1];
                __nv_bfloat162 h23; h23.x = h[2]; h23.y = h[3];
                __nv_bfloat162 l01; l01.x = l[0]; l01.y = l[1];
                __nv_bfloat162 l23; l23.x = l[2]; l23.y = l[3];
                *(__nv_bfloat162*)(g_ah + off)     = h01;
                *(__nv_bfloat162*)(g_ah + off + 2) = h23;
                *(__nv_bfloat162*)(g_al + off)     = l01;
                *(__nv_bfloat162*)(g_al + off + 2) = l23;
            }
        }
    }
}

// ---------------------------------------------------------------------------
// Launch
// ---------------------------------------------------------------------------
extern "C" void kernel_launch(void* const* d_in, const int* in_sizes, int n_in,
                              void* d_out, int out_size)
{
    const float* x     = (const float*)d_in[0];
    const float* pos   = (const float*)d_in[1];
    const int*   batch = (const int*)d_in[2];
    const float* Wq    = (const float*)d_in[3];
    const float* bq    = (const float*)d_in[4];
    const float* Wv    = (const float*)d_in[5];
    const float* bv    = (const float*)d_in[6];
    const float* Wo    = (const float*)d_in[7];
    const float* bo    = (const float*)d_in[8];
    const float* freqs = (const float*)d_in[9];
    float* out = (float*)d_out;

    float *gq, *gv, *gk, *gbqv;
    __nv_bfloat16 *gxh, *gxl, *gah, *gal, *gwqvh, *gwqvl, *gwoh, *gwol;
    cudaGetSymbolAddress((void**)&gq, g_q);
    cudaGetSymbolAddress((void**)&gv, g_v);
    cudaGetSymbolAddress((void**)&gk, g_k);
    cudaGetSymbolAddress((void**)&gbqv, g_bqv);
    cudaGetSymbolAddress((void**)&gxh, g_xh);
    cudaGetSymbolAddress((void**)&gxl, g_xl);
    cudaGetSymbolAddress((void**)&gah, g_ah);
    cudaGetSymbolAddress((void**)&gal, g_al);
    cudaGetSymbolAddress((void**)&gwqvh, g_wqvh);
    cudaGetSymbolAddress((void**)&gwqvl, g_wqvl);
    cudaGetSymbolAddress((void**)&gwoh, g_woh);
    cudaGetSymbolAddress((void**)&gwol, g_wol);

    cudaFuncSetAttribute(gemm_mma,
                         cudaFuncAttributeMaxDynamicSharedMemorySize, GEMM_SMEM);

    // 1) bf16 hi/lo conversion; weight transpose+split
    convert_x_kernel<<<(NN * CCH / 4 + 255) / 256, 256>>>(x);
    prep_w_kernel<<<(NQV * CCH + CCH * EE + 255) / 256, 256>>>(Wq, Wv, Wo, bq, bv);

    // 2) fused QV projection + RoPE epilogue -> g_q (rot), g_k (rot ones), g_v
    gemm_mma<<<dim3(NQV / 128, NN / 128), 256, GEMM_SMEM>>>(
        gxh, gxl, gwqvh, gwqvl, gbqv, gq, gv, gk, pos, freqs, CCH, 1);

    // 3) kv = segsum(k outer v) / 512
    kv_kernel<<<dim3(GG, NGRAPH), 256>>>(batch);

    // 4) attn = q . kv[batch] -> bf16 hi/lo
    attn_kernel<<<dim3(16, NGRAPH), 256>>>(batch);

    // 5) out = attn @ Wo + bo
    gemm_mma<<<dim3(EE / 128, NN / 128), 256, GEMM_SMEM>>>(
        gah, gal, gwoh, gwol, bo, out, out, nullptr, nullptr, nullptr, EE, 0);
}

// round 5
// speedup vs baseline: 1.8621x; 1.0549x over previous
#include <cuda_runtime.h>
#include <cuda_bf16.h>
#include <cstdint>
#include <cstddef>

// Problem constants
#define NN 32768
#define CCH 384
#define EE 384
#define GG 12
#define DD 32
#define PPAIR 16
#define NGRAPH 64
#define NQV 768

#define SW64(off) ((off) ^ (((off) >> 3) & 0x30))

// ---------------------------------------------------------------------------
// Scratch
// ---------------------------------------------------------------------------
__device__ float g_q[(size_t)NN * EE];
__device__ float g_v[(size_t)NN * EE];
__device__ float g_k[(size_t)NN * EE];
__device__ float g_kv[(size_t)NGRAPH * GG * DD * DD];
__device__ __nv_bfloat16 g_xh[(size_t)NN * CCH];
__device__ __nv_bfloat16 g_xl[(size_t)NN * CCH];
__device__ __nv_bfloat16 g_ah[(size_t)NN * EE];
__device__ __nv_bfloat16 g_al[(size_t)NN * EE];
__device__ __nv_bfloat16 g_wqvh[(size_t)NQV * CCH];
__device__ __nv_bfloat16 g_wqvl[(size_t)NQV * CCH];
__device__ __nv_bfloat16 g_woh[(size_t)CCH * EE];
__device__ __nv_bfloat16 g_wol[(size_t)CCH * EE];
__device__ float g_bqv[NQV];

// ---------------------------------------------------------------------------
// PTX wrappers (sm_80-baseline only)
// ---------------------------------------------------------------------------
__device__ __forceinline__ uint32_t smem_u32(const void* p) {
    uint32_t a;
    asm("{ .reg .u64 t; cvta.to.shared.u64 t, %1; cvt.u32.u64 %0, t; }"
        : "=r"(a) : "l"(p));
    return a;
}
__device__ __forceinline__ void cp_async16(uint32_t dst, const void* src) {
    asm volatile("cp.async.cg.shared.global [%0], [%1], 16;"
                 :: "r"(dst), "l"(src));
}
__device__ __forceinline__ void cp_commit() {
    asm volatile("cp.async.commit_group;");
}
__device__ __forceinline__ void cp_wait1() {
    asm volatile("cp.async.wait_group 1;");
}
__device__ __forceinline__ void cp_wait0() {
    asm volatile("cp.async.wait_group 0;");
}
__device__ __forceinline__ void ldm4(uint32_t* r, uint32_t addr) {
    asm volatile("ldmatrix.sync.aligned.m8n8.x4.shared.b16 {%0,%1,%2,%3}, [%4];"
                 : "=r"(r[0]), "=r"(r[1]), "=r"(r[2]), "=r"(r[3]) : "r"(addr));
}
__device__ __forceinline__ void mma_bf16(float* c, const uint32_t* a,
                                         const uint32_t b0, const uint32_t b1) {
    asm volatile(
        "mma.sync.aligned.m16n8k16.row.col.f32.bf16.bf16.f32 "
        "{%0,%1,%2,%3}, {%4,%5,%6,%7}, {%8,%9}, {%0,%1,%2,%3};"
        : "+f"(c[0]), "+f"(c[1]), "+f"(c[2]), "+f"(c[3])
        : "r"(a[0]), "r"(a[1]), "r"(a[2]), "r"(a[3]), "r"(b0), "r"(b1));
}

// ---------------------------------------------------------------------------
// Pipelined bf16x2 tensor GEMM, 128x128 tile, BK=32 (64B rows, SW64),
// 2-stage cp.async, 32KB/stage -> 64KB total -> 2 CTAs/SM.
// D = Ah*Bh + Al*Bh + Ah*Bl (fp32 accum).
// mode 1 = QV projection with RoPE fused into Q-half epilogue.
// ---------------------------------------------------------------------------
#define STAGE_BYTES 32768
#define GEMM_SMEM (2 * STAGE_BYTES)

__global__ __launch_bounds__(256, 2) void gemm_mma(
    const __nv_bfloat16* __restrict__ Ah, const __nv_bfloat16* __restrict__ Al,
    const __nv_bfloat16* __restrict__ Bh, const __nv_bfloat16* __restrict__ Bl,
    const float* __restrict__ bias, float* __restrict__ outQ,
    float* __restrict__ outV, float* __restrict__ outK,
    const float* __restrict__ pos, const float* __restrict__ freqs,
    int kTot, int mode)
{
    extern __shared__ char smem[];
    const uint32_t uS = smem_u32(smem);

    const int tid = threadIdx.x;
    const int bm = blockIdx.y * 128;
    const int bn = blockIdx.x * 128;

    // loader: row = tid>>1 (0..127), two 16B cols at (tid&1)*2 + {0,1}
    const int lrow = tid >> 1;
    const int lc = (tid & 1) * 2;
    const char* gA_h = (const char*)(Ah + (size_t)(bm + lrow) * kTot);
    const char* gA_l = (const char*)(Al + (size_t)(bm + lrow) * kTot);
    const char* gB_h = (const char*)(Bh + (size_t)(bn + lrow) * kTot);
    const char* gB_l = (const char*)(Bl + (size_t)(bn + lrow) * kTot);
    uint32_t sw[2];
#pragma unroll
    for (int i = 0; i < 2; i++)
        sw[i] = SW64((uint32_t)lrow * 64 + (lc + i) * 16);

    const int wid = tid >> 5, lane = tid & 31;
    const int wm = (wid & 3) * 32;
    const int wn = (wid >> 2) * 64;

    const uint32_t aRowOff = (uint32_t)(wm + (lane & 15)) * 64;
    const uint32_t aByte = (uint32_t)(lane >> 4) * 16;
    const uint32_t bRowOff =
        (uint32_t)(wn + ((lane >> 4) << 3) + (lane & 7)) * 64;
    const uint32_t bByte = (uint32_t)((lane >> 3) & 1) * 16;

    float acc[2][8][4];
#pragma unroll
    for (int mt = 0; mt < 2; mt++)
#pragma unroll
        for (int nt = 0; nt < 8; nt++)
#pragma unroll
            for (int j = 0; j < 4; j++) acc[mt][nt][j] = 0.f;

    const int nIter = kTot / 32;

    // prologue: stage 0
#pragma unroll
    for (int i = 0; i < 2; i++) {
        const int go = (lc + i) * 16;
        cp_async16(uS + sw[i], gA_h + go);
        cp_async16(uS + 8192 + sw[i], gA_l + go);
        cp_async16(uS + 16384 + sw[i], gB_h + go);
        cp_async16(uS + 24576 + sw[i], gB_l + go);
    }
    cp_commit();

    for (int c = 0; c < nIter; c++) {
        if (c + 1 < nIter) {
            const uint32_t sb = uS + ((c + 1) & 1) * STAGE_BYTES;
            const int k0b = (c + 1) * 64;
#pragma unroll
            for (int i = 0; i < 2; i++) {
                const int go = k0b + (lc + i) * 16;
                cp_async16(sb + sw[i], gA_h + go);
                cp_async16(sb + 8192 + sw[i], gA_l + go);
                cp_async16(sb + 16384 + sw[i], gB_h + go);
                cp_async16(sb + 24576 + sw[i], gB_l + go);
            }
            cp_commit();
            cp_wait1();
        } else {
            cp_wait0();
        }
        __syncthreads();

        const uint32_t st = uS + (c & 1) * STAGE_BYTES;
        const uint32_t uAh = st, uAl = st + 8192;
        const uint32_t uBh = st + 16384, uBl = st + 24576;

#pragma unroll
        for (int ks = 0; ks < 2; ks++) {
            const uint32_t kb = (uint32_t)ks * 32;
            uint32_t ax[2][4], alx[2][4], bx[4][4];
#pragma unroll
            for (int mt = 0; mt < 2; mt++)
                ldm4(ax[mt], uAh + SW64(aRowOff + mt * 1024 + kb + aByte));
#pragma unroll
            for (int nt2 = 0; nt2 < 4; nt2++)
                ldm4(bx[nt2], uBh + SW64(bRowOff + nt2 * 1024 + kb + bByte));
#pragma unroll
            for (int mt = 0; mt < 2; mt++)
#pragma unroll
                for (int nt = 0; nt < 8; nt++)
                    mma_bf16(acc[mt][nt], ax[mt],
                             bx[nt >> 1][(nt & 1) * 2], bx[nt >> 1][(nt & 1) * 2 + 1]);
#pragma unroll
            for (int mt = 0; mt < 2; mt++)
                ldm4(alx[mt], uAl + SW64(aRowOff + mt * 1024 + kb + aByte));
#pragma unroll
            for (int mt = 0; mt < 2; mt++)
#pragma unroll
                for (int nt = 0; nt < 8; nt++)
                    mma_bf16(acc[mt][nt], alx[mt],
                             bx[nt >> 1][(nt & 1) * 2], bx[nt >> 1][(nt & 1) * 2 + 1]);
#pragma unroll
            for (int nt2 = 0; nt2 < 4; nt2++)
                ldm4(bx[nt2], uBl + SW64(bRowOff + nt2 * 1024 + kb + bByte));
#pragma unroll
            for (int mt = 0; mt < 2; mt++)
#pragma unroll
                for (int nt = 0; nt < 8; nt++)
                    mma_bf16(acc[mt][nt], ax[mt],
                             bx[nt >> 1][(nt & 1) * 2], bx[nt >> 1][(nt & 1) * 2 + 1]);
        }
        __syncthreads();
    }

    // ------------------------- epilogue -------------------------
    const int r0 = bm + wm + (lane >> 2);
    const int cb = wn + (lane & 3) * 2;

    if (mode == 1 && bn < EE) {
        float px[4], py[4], pz[4];
        int rr[4];
#pragma unroll
        for (int j = 0; j < 4; j++) {
            rr[j] = r0 + (j >> 1) * 16 + (j & 1) * 8;
            px[j] = pos[rr[j] * 3 + 0];
            py[j] = pos[rr[j] * 3 + 1];
            pz[j] = pos[rr[j] * 3 + 2];
        }
#pragma unroll
        for (int nt = 0; nt < 8; nt++) {
            const int gc = bn + cb + nt * 8;          // even global column
            const int g = gc >> 5;
            const int p = (gc & 31) >> 1;
            const float* f = freqs + ((size_t)g * PPAIR + p) * 3;
            const float fx = f[0], fy = f[1], fz = f[2];
            const float b0 = bias[gc], b1 = bias[gc + 1];
#pragma unroll
            for (int mt = 0; mt < 2; mt++) {
#pragma unroll
                for (int h = 0; h < 2; h++) {
                    const int j = mt * 2 + h;
                    const float ph = px[j] * fx + py[j] * fy + pz[j] * fz;
                    const float sn = __sinf(ph);
                    const float cs = __cosf(ph);
                    const float x1 = acc[mt][nt][h * 2 + 0] + b0;
                    const float x2 = acc[mt][nt][h * 2 + 1] + b1;
                    float2 qv, kv;
                    qv.x = x1 * cs - x2 * sn;
                    qv.y = x1 * sn + x2 * cs;
                    kv.x = cs - sn;
                    kv.y = sn + cs;
                    const size_t o = (size_t)rr[j] * EE + gc;
                    *(float2*)&outQ[o] = qv;
                    *(float2*)&outK[o] = kv;
                }
            }
        }
    } else {
        float* dst = (mode == 1) ? outV : outQ;
        const int bcol = (mode == 1) ? bn - EE : bn;
#pragma unroll
        for (int mt = 0; mt < 2; mt++) {
            const int row = r0 + mt * 16;
#pragma unroll
            for (int nt = 0; nt < 8; nt++) {
                const int col = cb + nt * 8;
                const float b0 = bias[bn + col];
                const float b1 = bias[bn + col + 1];
                float2 v0, v1;
                v0.x = acc[mt][nt][0] + b0; v0.y = acc[mt][nt][1] + b1;
                v1.x = acc[mt][nt][2] + b0; v1.y = acc[mt][nt][3] + b1;
                *(float2*)&dst[(size_t)row * EE + bcol + col]       = v0;
                *(float2*)&dst[(size_t)(row + 8) * EE + bcol + col] = v1;
            }
        }
    }
}

// ---------------------------------------------------------------------------
// x -> bf16 hi/lo split
// ---------------------------------------------------------------------------
__global__ void convert_x_kernel(const float* __restrict__ x)
{
    int i = (blockIdx.x * blockDim.x + threadIdx.x) * 4;
    if (i >= NN * CCH) return;
    float4 v = *(const float4*)(x + i);
    float vv[4] = {v.x, v.y, v.z, v.w};
    __nv_bfloat16 h[4], l[4];
#pragma unroll
    for (int j = 0; j < 4; j++) {
        h[j] = __float2bfloat16(vv[j]);
        l[j] = __float2bfloat16(vv[j] - __bfloat162float(h[j]));
    }
    __nv_bfloat162 h01; h01.x = h[0]; h01.y = h[1];
    __nv_bfloat162 h23; h23.x = h[2]; h23.y = h[3];
    __nv_bfloat162 l01; l01.x = l[0]; l01.y = l[1];
    __nv_bfloat162 l23; l23.x = l[2]; l23.y = l[3];
    *(__nv_bfloat162*)(g_xh + i)     = h01;
    *(__nv_bfloat162*)(g_xh + i + 2) = h23;
    *(__nv_bfloat162*)(g_xl + i)     = l01;
    *(__nv_bfloat162*)(g_xl + i + 2) = l23;
}

// ---------------------------------------------------------------------------
// Transpose + split weights
// ---------------------------------------------------------------------------
__global__ void prep_w_kernel(const float* __restrict__ Wq,
                              const float* __restrict__ Wv,
                              const float* __restrict__ Wo,
                              const float* __restrict__ bq,
                              const float* __restrict__ bv)
{
    int idx = blockIdx.x * blockDim.x + threadIdx.x;
    const int T1 = NQV * CCH;
    if (idx < T1) {
        int n = idx / CCH, k = idx % CCH;
        float f = (n < EE) ? Wq[(size_t)k * EE + n] : Wv[(size_t)k * EE + (n - EE)];
        __nv_bfloat16 h = __float2bfloat16(f);
        g_wqvh[idx] = h;
        g_wqvl[idx] = __float2bfloat16(f - __bfloat162float(h));
    } else if (idx < T1 + CCH * EE) {
        int j = idx - T1;
        int n = j / EE, k = j % EE;
        float f = Wo[(size_t)k * CCH + n];
        __nv_bfloat16 h = __float2bfloat16(f);
        g_woh[j] = h;
        g_wol[j] = __float2bfloat16(f - __bfloat162float(h));
    }
    if (idx < NQV) g_bqv[idx] = (idx < EE) ? bq[idx] : bv[idx - EE];
}

// ---------------------------------------------------------------------------
// Inline segment bound (batch is sorted)
// ---------------------------------------------------------------------------
__device__ __forceinline__ int seg_lower(const int* __restrict__ batch, int t)
{
    int lo = 0, hi = NN;
    while (lo < hi) {
        int mid = (lo + hi) >> 1;
        if (batch[mid] < t) lo = mid + 1; else hi = mid;
    }
    return lo;
}

// ---------------------------------------------------------------------------
// KV segment reduction, v2: block = (graph b, 1/16 of its nodes).
// Each thread accumulates kv[g][d][e0..e0+3] for ALL 12 groups in registers
// (48 regs), full coalesced row staging, atomicAdd combine into zeroed g_kv.
// ---------------------------------------------------------------------------
#define KVSPLIT 16
#define KVCH 8
__global__ __launch_bounds__(256) void kv_kernel(const int* __restrict__ batch)
{
    const int b = blockIdx.y;
    const int s = seg_lower(batch, b);
    const int e = seg_lower(batch, b + 1);
    const int len = e - s;
    if (len <= 0) return;
    const int per = (len + KVSPLIT - 1) / KVSPLIT;
    const int rs = s + blockIdx.x * per;
    const int re = min(e, rs + per);
    if (rs >= re) return;

    const int tid = threadIdx.x;
    const int d = tid >> 3;           // 0..31
    const int e0 = (tid & 7) << 2;    // 0..28

    __shared__ float sk[KVCH][CCH];
    __shared__ float sv[KVCH][CCH];

    float acc[GG][4];
#pragma unroll
    for (int g = 0; g < GG; g++)
#pragma unroll
        for (int j = 0; j < 4; j++) acc[g][j] = 0.f;

    for (int n0 = rs; n0 < re; n0 += KVCH) {
        const int cnt = min(KVCH, re - n0);
        __syncthreads();
        // stage cnt full rows of k and v (coalesced float4)
#pragma unroll
        for (int j = 0; j < 6; j++) {
            int lin = tid + j * 256;              // [0,1536)
            int half = lin >= 768;
            int rem = lin - half * 768;
            int node = rem / 96;
            int c16 = rem - node * 96;
            if (node < cnt) {
                const float* src = (half ? g_v : g_k)
                    + (size_t)(n0 + node) * CCH + c16 * 4;
                float4 val = *(const float4*)src;
                float* dst = (half ? &sv[node][c16 * 4] : &sk[node][c16 * 4]);
                *(float4*)dst = val;
            }
        }
        __syncthreads();
        for (int c = 0; c < cnt; c++) {
#pragma unroll
            for (int g = 0; g < GG; g++) {
                const float kd = sk[c][g * DD + d];
                const float4 fv = *(const float4*)&sv[c][g * DD + e0];
                acc[g][0] += kd * fv.x;
                acc[g][1] += kd * fv.y;
                acc[g][2] += kd * fv.z;
                acc[g][3] += kd * fv.w;
            }
        }
    }

#pragma unroll
    for (int g = 0; g < GG; g++) {
        float* dst = g_kv + (((size_t)b * GG + g) * DD + d) * DD + e0;
        atomicAdd(dst + 0, acc[g][0]);
        atomicAdd(dst + 1, acc[g][1]);
        atomicAdd(dst + 2, acc[g][2]);
        atomicAdd(dst + 3, acc[g][3]);
    }
}

// ---------------------------------------------------------------------------
// Apply: attn = q . kv[batch] (kv raw; scale 1/512 applied here);
// emits bf16 hi/lo for the final GEMM
// ---------------------------------------------------------------------------
#define ACH 128
__global__ __launch_bounds__(256) void attn_kernel(const int* __restrict__ batch)
{
    int c = blockIdx.x;
    int b = blockIdx.y;
    int s = seg_lower(batch, b);
    int e = seg_lower(batch, b + 1);
    int nbase = s + c * ACH;
    if (nbase >= e) return;
    int cnt = min(ACH, e - nbase);
    int tid = threadIdx.x;

    __shared__ float Qs[DD][ACH + 4];
    __shared__ float Ks[DD][DD];

    int trow = (tid >> 3) * 4;
    int tcol = (tid & 7) * 4;

    const float inv = 1.0f / 512.0f;

    for (int g = 0; g < GG; g++) {
        __syncthreads();
        for (int i = tid; i < ACH * DD; i += 256) {
            int nn = i >> 5, kk = i & 31;
            Qs[kk][nn] = (nn < cnt)
                ? g_q[(size_t)(nbase + nn) * EE + g * DD + kk] : 0.f;
        }
        {
            const float* kvp = g_kv + ((size_t)b * GG + g) * DD * DD;
            for (int i = tid; i < DD * DD; i += 256)
                (&Ks[0][0])[i] = kvp[i] * inv;
        }
        __syncthreads();

        float acc[4][4];
#pragma unroll
        for (int i = 0; i < 4; i++)
#pragma unroll
            for (int j = 0; j < 4; j++) acc[i][j] = 0.f;

#pragma unroll
        for (int k = 0; k < DD; k++) {
            float ra[4], rb[4];
            *(float4*)ra = *(const float4*)&Qs[k][trow];
            *(float4*)rb = *(const float4*)&Ks[k][tcol];
#pragma unroll
            for (int i = 0; i < 4; i++)
#pragma unroll
                for (int j = 0; j < 4; j++)
                    acc[i][j] += ra[i] * rb[j];
        }

#pragma unroll
        for (int i = 0; i < 4; i++) {
            int r = trow + i;
            if (r < cnt) {
                size_t off = (size_t)(nbase + r) * EE + g * DD + tcol;
                __nv_bfloat16 h[4], l[4];
#pragma unroll
                for (int j = 0; j < 4; j++) {
                    h[j] = __float2bfloat16(acc[i][j]);
                    l[j] = __float2bfloat16(acc[i][j] - __bfloat162float(h[j]));
                }
                __nv_bfloat162 h01; h01.x = h[0]; h01.y = h[1];
                __nv_bfloat162 h23; h23.x = h[2]; h23.y = h[3];
                __nv_bfloat162 l01; l01.x = l[0]; l01.y = l[1];
                __nv_bfloat162 l23; l23.x = l[2]; l23.y = l[3];
                *(__nv_bfloat162*)(g_ah + off)     = h01;
                *(__nv_bfloat162*)(g_ah + off + 2) = h23;
                *(__nv_bfloat162*)(g_al + off)     = l01;
                *(__nv_bfloat162*)(g_al + off + 2) = l23;
            }
        }
    }
}

// ---------------------------------------------------------------------------
// Launch
// ---------------------------------------------------------------------------
extern "C" void kernel_launch(void* const* d_in, const int* in_sizes, int n_in,
                              void* d_out, int out_size)
{
    const float* x     = (const float*)d_in[0];
    const float* pos   = (const float*)d_in[1];
    const int*   batch = (const int*)d_in[2];
    const float* Wq    = (const float*)d_in[3];
    const float* bq    = (const float*)d_in[4];
    const float* Wv    = (const float*)d_in[5];
    const float* bv    = (const float*)d_in[6];
    const float* Wo    = (const float*)d_in[7];
    const float* bo    = (const float*)d_in[8];
    const float* freqs = (const float*)d_in[9];
    float* out = (float*)d_out;

    float *gq, *gv, *gk, *gkv, *gbqv;
    __nv_bfloat16 *gxh, *gxl, *gah, *gal, *gwqvh, *gwqvl, *gwoh, *gwol;
    cudaGetSymbolAddress((void**)&gq, g_q);
    cudaGetSymbolAddress((void**)&gv, g_v);
    cudaGetSymbolAddress((void**)&gk, g_k);
    cudaGetSymbolAddress((void**)&gkv, g_kv);
    cudaGetSymbolAddress((void**)&gbqv, g_bqv);
    cudaGetSymbolAddress((void**)&gxh, g_xh);
    cudaGetSymbolAddress((void**)&gxl, g_xl);
    cudaGetSymbolAddress((void**)&gah, g_ah);
    cudaGetSymbolAddress((void**)&gal, g_al);
    cudaGetSymbolAddress((void**)&gwqvh, g_wqvh);
    cudaGetSymbolAddress((void**)&gwqvl, g_wqvl);
    cudaGetSymbolAddress((void**)&gwoh, g_woh);
    cudaGetSymbolAddress((void**)&gwol, g_wol);

    cudaFuncSetAttribute(gemm_mma,
                         cudaFuncAttributeMaxDynamicSharedMemorySize, GEMM_SMEM);

    // 1) bf16 hi/lo conversion; weight transpose+split; zero kv accumulator
    convert_x_kernel<<<(NN * CCH / 4 + 255) / 256, 256>>>(x);
    prep_w_kernel<<<(NQV * CCH + CCH * EE + 255) / 256, 256>>>(Wq, Wv, Wo, bq, bv);
    cudaMemsetAsync(gkv, 0, (size_t)NGRAPH * GG * DD * DD * sizeof(float));

    // 2) fused QV projection + RoPE epilogue -> g_q (rot), g_k (rot ones), g_v
    gemm_mma<<<dim3(NQV / 128, NN / 128), 256, GEMM_SMEM>>>(
        gxh, gxl, gwqvh, gwqvl, gbqv, gq, gv, gk, pos, freqs, CCH, 1);

    // 3) kv = segsum(k outer v)  (raw; scaled at use)
    kv_kernel<<<dim3(KVSPLIT, NGRAPH), 256>>>(batch);

    // 4) attn = q . kv[batch]/512 -> bf16 hi/lo
    attn_kernel<<<dim3(16, NGRAPH), 256>>>(batch);

    // 5) out = attn @ Wo + bo
    gemm_mma<<<dim3(EE / 128, NN / 128), 256, GEMM_SMEM>>>(
        gah, gal, gwoh, gwol, bo, out, out, nullptr, nullptr, nullptr, EE, 0);
}

// round 6
// speedup vs baseline: 1.9957x; 1.0718x over previous
#include <cuda_runtime.h>
#include <cuda_bf16.h>
#include <cstdint>
#include <cstddef>

// Problem constants
#define NN 32768
#define CCH 384
#define EE 384
#define GG 12
#define DD 32
#define PPAIR 16
#define NGRAPH 64
#define NQV 768

#define SW64(off) ((off) ^ (((off) >> 3) & 0x30))

// ---------------------------------------------------------------------------
// Scratch
// ---------------------------------------------------------------------------
__device__ float g_q[(size_t)NN * EE];
__device__ float g_v[(size_t)NN * EE];
__device__ float g_k[(size_t)NN * EE];
__device__ float g_kv[(size_t)2 * NGRAPH * GG * DD * DD];   // 2 node-splits
__device__ __nv_bfloat16 g_xh[(size_t)NN * CCH];
__device__ __nv_bfloat16 g_xl[(size_t)NN * CCH];
__device__ __nv_bfloat16 g_ah[(size_t)NN * EE];
__device__ __nv_bfloat16 g_al[(size_t)NN * EE];
__device__ __nv_bfloat16 g_wqvh[(size_t)NQV * CCH];
__device__ __nv_bfloat16 g_wqvl[(size_t)NQV * CCH];
__device__ __nv_bfloat16 g_woh[(size_t)CCH * EE];
__device__ __nv_bfloat16 g_wol[(size_t)CCH * EE];
__device__ float g_bqv[NQV];

// ---------------------------------------------------------------------------
// PTX wrappers (sm_80-baseline only)
// ---------------------------------------------------------------------------
__device__ __forceinline__ uint32_t smem_u32(const void* p) {
    uint32_t a;
    asm("{ .reg .u64 t; cvta.to.shared.u64 t, %1; cvt.u32.u64 %0, t; }"
        : "=r"(a) : "l"(p));
    return a;
}
__device__ __forceinline__ void cp_async16(uint32_t dst, const void* src) {
    asm volatile("cp.async.cg.shared.global [%0], [%1], 16;"
                 :: "r"(dst), "l"(src));
}
__device__ __forceinline__ void cp_commit() {
    asm volatile("cp.async.commit_group;");
}
__device__ __forceinline__ void cp_wait2() {
    asm volatile("cp.async.wait_group 2;");
}
__device__ __forceinline__ void cp_wait1() {
    asm volatile("cp.async.wait_group 1;");
}
__device__ __forceinline__ void cp_wait0() {
    asm volatile("cp.async.wait_group 0;");
}
__device__ __forceinline__ void ldm4(uint32_t* r, uint32_t addr) {
    asm volatile("ldmatrix.sync.aligned.m8n8.x4.shared.b16 {%0,%1,%2,%3}, [%4];"
                 : "=r"(r[0]), "=r"(r[1]), "=r"(r[2]), "=r"(r[3]) : "r"(addr));
}
__device__ __forceinline__ void mma_bf16(float* c, const uint32_t* a,
                                         const uint32_t b0, const uint32_t b1) {
    asm volatile(
        "mma.sync.aligned.m16n8k16.row.col.f32.bf16.bf16.f32 "
        "{%0,%1,%2,%3}, {%4,%5,%6,%7}, {%8,%9}, {%0,%1,%2,%3};"
        : "+f"(c[0]), "+f"(c[1]), "+f"(c[2]), "+f"(c[3])
        : "r"(a[0]), "r"(a[1]), "r"(a[2]), "r"(a[3]), "r"(b0), "r"(b1));
}

// ---------------------------------------------------------------------------
// Pipelined bf16x2 tensor GEMM, 128x128 tile, BK=32 (64B rows, SW64),
// 3-stage cp.async, 32KB/stage -> 96KB total -> 2 CTAs/SM.
// D = Ah*Bh + Al*Bh + Ah*Bl (fp32 accum).
// mode 1 = QV projection with RoPE fused into Q-half epilogue.
// ---------------------------------------------------------------------------
#define STAGE_BYTES 32768
#define NSTAGE 3
#define GEMM_SMEM (NSTAGE * STAGE_BYTES)

__global__ __launch_bounds__(256, 2) void gemm_mma(
    const __nv_bfloat16* __restrict__ Ah, const __nv_bfloat16* __restrict__ Al,
    const __nv_bfloat16* __restrict__ Bh, const __nv_bfloat16* __restrict__ Bl,
    const float* __restrict__ bias, float* __restrict__ outQ,
    float* __restrict__ outV, float* __restrict__ outK,
    const float* __restrict__ pos, const float* __restrict__ freqs,
    int kTot, int mode)
{
    extern __shared__ char smem[];
    const uint32_t uS = smem_u32(smem);

    const int tid = threadIdx.x;
    const int bm = blockIdx.y * 128;
    const int bn = blockIdx.x * 128;

    // loader: row = tid>>1 (0..127), two 16B cols at (tid&1)*2 + {0,1}
    const int lrow = tid >> 1;
    const int lc = (tid & 1) * 2;
    const char* gA_h = (const char*)(Ah + (size_t)(bm + lrow) * kTot);
    const char* gA_l = (const char*)(Al + (size_t)(bm + lrow) * kTot);
    const char* gB_h = (const char*)(Bh + (size_t)(bn + lrow) * kTot);
    const char* gB_l = (const char*)(Bl + (size_t)(bn + lrow) * kTot);
    uint32_t sw[2];
#pragma unroll
    for (int i = 0; i < 2; i++)
        sw[i] = SW64((uint32_t)lrow * 64 + (lc + i) * 16);

    const int wid = tid >> 5, lane = tid & 31;
    const int wm = (wid & 3) * 32;
    const int wn = (wid >> 2) * 64;

    const uint32_t aRowOff = (uint32_t)(wm + (lane & 15)) * 64;
    const uint32_t aByte = (uint32_t)(lane >> 4) * 16;
    const uint32_t bRowOff =
        (uint32_t)(wn + ((lane >> 4) << 3) + (lane & 7)) * 64;
    const uint32_t bByte = (uint32_t)((lane >> 3) & 1) * 16;

    float acc[2][8][4];
#pragma unroll
    for (int mt = 0; mt < 2; mt++)
#pragma unroll
        for (int nt = 0; nt < 8; nt++)
#pragma unroll
            for (int j = 0; j < 4; j++) acc[mt][nt][j] = 0.f;

    const int nIter = kTot / 32;

    // prologue: stages 0 and 1
#pragma unroll
    for (int s = 0; s < 2; s++) {
        const uint32_t sb = uS + s * STAGE_BYTES;
        const int k0b = s * 64;
#pragma unroll
        for (int i = 0; i < 2; i++) {
            const int go = k0b + (lc + i) * 16;
            cp_async16(sb + sw[i], gA_h + go);
            cp_async16(sb + 8192 + sw[i], gA_l + go);
            cp_async16(sb + 16384 + sw[i], gB_h + go);
            cp_async16(sb + 24576 + sw[i], gB_l + go);
        }
        cp_commit();
    }

    int st = 0, ld = 2;
    for (int c = 0; c < nIter; c++) {
        if (c + 2 < nIter) {
            const uint32_t sb = uS + ld * STAGE_BYTES;
            const int k0b = (c + 2) * 64;
#pragma unroll
            for (int i = 0; i < 2; i++) {
                const int go = k0b + (lc + i) * 16;
                cp_async16(sb + sw[i], gA_h + go);
                cp_async16(sb + 8192 + sw[i], gA_l + go);
                cp_async16(sb + 16384 + sw[i], gB_h + go);
                cp_async16(sb + 24576 + sw[i], gB_l + go);
            }
            cp_commit();
            cp_wait2();
        } else if (c + 1 < nIter) {
            cp_wait1();
        } else {
            cp_wait0();
        }
        __syncthreads();

        const uint32_t base = uS + st * STAGE_BYTES;
        const uint32_t uAh = base, uAl = base + 8192;
        const uint32_t uBh = base + 16384, uBl = base + 24576;

#pragma unroll
        for (int ks = 0; ks < 2; ks++) {
            const uint32_t kb = (uint32_t)ks * 32;
            uint32_t ax[2][4], alx[2][4], bx[4][4];
#pragma unroll
            for (int mt = 0; mt < 2; mt++)
                ldm4(ax[mt], uAh + SW64(aRowOff + mt * 1024 + kb + aByte));
#pragma unroll
            for (int nt2 = 0; nt2 < 4; nt2++)
                ldm4(bx[nt2], uBh + SW64(bRowOff + nt2 * 1024 + kb + bByte));
#pragma unroll
            for (int mt = 0; mt < 2; mt++)
#pragma unroll
                for (int nt = 0; nt < 8; nt++)
                    mma_bf16(acc[mt][nt], ax[mt],
                             bx[nt >> 1][(nt & 1) * 2], bx[nt >> 1][(nt & 1) * 2 + 1]);
#pragma unroll
            for (int mt = 0; mt < 2; mt++)
                ldm4(alx[mt], uAl + SW64(aRowOff + mt * 1024 + kb + aByte));
#pragma unroll
            for (int mt = 0; mt < 2; mt++)
#pragma unroll
                for (int nt = 0; nt < 8; nt++)
                    mma_bf16(acc[mt][nt], alx[mt],
                             bx[nt >> 1][(nt & 1) * 2], bx[nt >> 1][(nt & 1) * 2 + 1]);
#pragma unroll
            for (int nt2 = 0; nt2 < 4; nt2++)
                ldm4(bx[nt2], uBl + SW64(bRowOff + nt2 * 1024 + kb + bByte));
#pragma unroll
            for (int mt = 0; mt < 2; mt++)
#pragma unroll
                for (int nt = 0; nt < 8; nt++)
                    mma_bf16(acc[mt][nt], ax[mt],
                             bx[nt >> 1][(nt & 1) * 2], bx[nt >> 1][(nt & 1) * 2 + 1]);
        }
        __syncthreads();
        st = (st == NSTAGE - 1) ? 0 : st + 1;
        ld = (ld == NSTAGE - 1) ? 0 : ld + 1;
    }

    // ------------------------- epilogue -------------------------
    const int r0 = bm + wm + (lane >> 2);
    const int cb = wn + (lane & 3) * 2;

    if (mode == 1 && bn < EE) {
        float px[4], py[4], pz[4];
        int rr[4];
#pragma unroll
        for (int j = 0; j < 4; j++) {
            rr[j] = r0 + (j >> 1) * 16 + (j & 1) * 8;
            px[j] = pos[rr[j] * 3 + 0];
            py[j] = pos[rr[j] * 3 + 1];
            pz[j] = pos[rr[j] * 3 + 2];
        }
#pragma unroll
        for (int nt = 0; nt < 8; nt++) {
            const int gc = bn + cb + nt * 8;          // even global column
            const int g = gc >> 5;
            const int p = (gc & 31) >> 1;
            const float* f = freqs + ((size_t)g * PPAIR + p) * 3;
            const float fx = f[0], fy = f[1], fz = f[2];
            const float b0 = bias[gc], b1 = bias[gc + 1];
#pragma unroll
            for (int mt = 0; mt < 2; mt++) {
#pragma unroll
                for (int h = 0; h < 2; h++) {
                    const int j = mt * 2 + h;
                    const float ph = px[j] * fx + py[j] * fy + pz[j] * fz;
                    const float sn = __sinf(ph);
                    const float cs = __cosf(ph);
                    const float x1 = acc[mt][nt][h * 2 + 0] + b0;
                    const float x2 = acc[mt][nt][h * 2 + 1] + b1;
                    float2 qv, kv;
                    qv.x = x1 * cs - x2 * sn;
                    qv.y = x1 * sn + x2 * cs;
                    kv.x = cs - sn;
                    kv.y = sn + cs;
                    const size_t o = (size_t)rr[j] * EE + gc;
                    *(float2*)&outQ[o] = qv;
                    *(float2*)&outK[o] = kv;
                }
            }
        }
    } else {
        float* dst = (mode == 1) ? outV : outQ;
        const int bcol = (mode == 1) ? bn - EE : bn;
#pragma unroll
        for (int mt = 0; mt < 2; mt++) {
            const int row = r0 + mt * 16;
#pragma unroll
            for (int nt = 0; nt < 8; nt++) {
                const int col = cb + nt * 8;
                const float b0 = bias[bn + col];
                const float b1 = bias[bn + col + 1];
                float2 v0, v1;
                v0.x = acc[mt][nt][0] + b0; v0.y = acc[mt][nt][1] + b1;
                v1.x = acc[mt][nt][2] + b0; v1.y = acc[mt][nt][3] + b1;
                *(float2*)&dst[(size_t)row * EE + bcol + col]       = v0;
                *(float2*)&dst[(size_t)(row + 8) * EE + bcol + col] = v1;
            }
        }
    }
}

// ---------------------------------------------------------------------------
// x -> bf16 hi/lo split
// ---------------------------------------------------------------------------
__global__ void convert_x_kernel(const float* __restrict__ x)
{
    int i = (blockIdx.x * blockDim.x + threadIdx.x) * 4;
    if (i >= NN * CCH) return;
    float4 v = *(const float4*)(x + i);
    float vv[4] = {v.x, v.y, v.z, v.w};
    __nv_bfloat16 h[4], l[4];
#pragma unroll
    for (int j = 0; j < 4; j++) {
        h[j] = __float2bfloat16(vv[j]);
        l[j] = __float2bfloat16(vv[j] - __bfloat162float(h[j]));
    }
    __nv_bfloat162 h01; h01.x = h[0]; h01.y = h[1];
    __nv_bfloat162 h23; h23.x = h[2]; h23.y = h[3];
    __nv_bfloat162 l01; l01.x = l[0]; l01.y = l[1];
    __nv_bfloat162 l23; l23.x = l[2]; l23.y = l[3];
    *(__nv_bfloat162*)(g_xh + i)     = h01;
    *(__nv_bfloat162*)(g_xh + i + 2) = h23;
    *(__nv_bfloat162*)(g_xl + i)     = l01;
    *(__nv_bfloat162*)(g_xl + i + 2) = l23;
}

// ---------------------------------------------------------------------------
// Transpose + split weights
// ---------------------------------------------------------------------------
__global__ void prep_w_kernel(const float* __restrict__ Wq,
                              const float* __restrict__ Wv,
                              const float* __restrict__ Wo,
                              const float* __restrict__ bq,
                              const float* __restrict__ bv)
{
    int idx = blockIdx.x * blockDim.x + threadIdx.x;
    const int T1 = NQV * CCH;
    if (idx < T1) {
        int n = idx / CCH, k = idx % CCH;
        float f = (n < EE) ? Wq[(size_t)k * EE + n] : Wv[(size_t)k * EE + (n - EE)];
        __nv_bfloat16 h = __float2bfloat16(f);
        g_wqvh[idx] = h;
        g_wqvl[idx] = __float2bfloat16(f - __bfloat162float(h));
    } else if (idx < T1 + CCH * EE) {
        int j = idx - T1;
        int n = j / EE, k = j % EE;
        float f = Wo[(size_t)k * CCH + n];
        __nv_bfloat16 h = __float2bfloat16(f);
        g_woh[j] = h;
        g_wol[j] = __float2bfloat16(f - __bfloat162float(h));
    }
    if (idx < NQV) g_bqv[idx] = (idx < EE) ? bq[idx] : bv[idx - EE];
}

// ---------------------------------------------------------------------------
// Inline segment bound (batch is sorted)
// ---------------------------------------------------------------------------
__device__ __forceinline__ int seg_lower(const int* __restrict__ batch, int t)
{
    int lo = 0, hi = NN;
    while (lo < hi) {
        int mid = (lo + hi) >> 1;
        if (batch[mid] < t) lo = mid + 1; else hi = mid;
    }
    return lo;
}

// ---------------------------------------------------------------------------
// KV segment reduction, v3: block = (group gi, node-split sp, graph b).
// 4-reg accumulator per thread, cp.async double-buffered 16-node staging,
// results stored to per-split kv buffers (no atomics, summed in attn).
// ---------------------------------------------------------------------------
#define KVSPLIT 2
#define KVCH 16
__global__ __launch_bounds__(256) void kv_kernel(const int* __restrict__ batch)
{
    const int bx = blockIdx.x;
    const int gi = bx >> 1;          // 0..11
    const int sp = bx & 1;           // node split 0/1
    const int b = blockIdx.y;
    const int s = seg_lower(batch, b);
    const int e = seg_lower(batch, b + 1);
    const int len = e - s;
    const int per = (len + KVSPLIT - 1) / KVSPLIT;
    const int rs = s + sp * per;
    const int re = min(e, rs + per);

    const int tid = threadIdx.x;
    const int d = tid >> 3;          // 0..31
    const int e0 = (tid & 7) << 2;   // 0..28

    __shared__ float sbuf[2][2][KVCH][DD];   // [stage][k/v][node][32]
    const uint32_t sb0 = smem_u32(&sbuf[0][0][0][0]);

    // loader mapping: one cp.async16 per thread per (stage, chunk)
    const int larr = tid >> 7;          // 0 = k, 1 = v
    const int lnode = (tid >> 3) & 15;  // 0..15
    const int lc4 = tid & 7;            // 0..7 (16B units)
    const float* lsrc = larr ? g_v : g_k;
    const uint32_t ldst0 =
        sb0 + (uint32_t)(((0 * 2 + larr) * KVCH + lnode) * DD + lc4 * 4) * 4;
    const uint32_t ldst1 =
        sb0 + (uint32_t)(((1 * 2 + larr) * KVCH + lnode) * DD + lc4 * 4) * 4;

    float a0 = 0.f, a1 = 0.f, a2 = 0.f, a3 = 0.f;

    if (rs < re) {
        // prologue: stage 0
        if (rs + lnode < re)
            cp_async16(ldst0,
                       lsrc + (size_t)(rs + lnode) * CCH + gi * DD + lc4 * 4);
        cp_commit();

        int st = 0;
        for (int n0 = rs; n0 < re; n0 += KVCH, st ^= 1) {
            const int nn = n0 + KVCH;
            if (nn < re) {
                if (nn + lnode < re)
                    cp_async16(st ? ldst0 : ldst1,
                               lsrc + (size_t)(nn + lnode) * CCH + gi * DD + lc4 * 4);
                cp_commit();
                cp_wait1();
            } else {
                cp_wait0();
            }
            __syncthreads();
            const int cnt = min(KVCH, re - n0);
            for (int c = 0; c < cnt; c++) {
                const float kd = sbuf[st][0][c][d];
                const float4 fv = *(const float4*)&sbuf[st][1][c][e0];
                a0 += kd * fv.x;
                a1 += kd * fv.y;
                a2 += kd * fv.z;
                a3 += kd * fv.w;
            }
            __syncthreads();
        }
    }

    float* dst = g_kv
        + ((((size_t)sp * NGRAPH + b) * GG + gi) * DD + d) * DD + e0;
    dst[0] = a0; dst[1] = a1; dst[2] = a2; dst[3] = a3;
}

// ---------------------------------------------------------------------------
// Apply: attn = q . kv[batch] (sums the 2 split buffers, scales by 1/512);
// emits bf16 hi/lo for the final GEMM
// ---------------------------------------------------------------------------
#define ACH 128
__global__ __launch_bounds__(256) void attn_kernel(const int* __restrict__ batch)
{
    int c = blockIdx.x;
    int b = blockIdx.y;
    int s = seg_lower(batch, b);
    int e = seg_lower(batch, b + 1);
    int nbase = s + c * ACH;
    if (nbase >= e) return;
    int cnt = min(ACH, e - nbase);
    int tid = threadIdx.x;

    __shared__ float Qs[DD][ACH + 4];
    __shared__ float Ks[DD][DD];

    int trow = (tid >> 3) * 4;
    int tcol = (tid & 7) * 4;

    const float inv = 1.0f / 512.0f;

    for (int g = 0; g < GG; g++) {
        __syncthreads();
        for (int i = tid; i < ACH * DD; i += 256) {
            int nn = i >> 5, kk = i & 31;
            Qs[kk][nn] = (nn < cnt)
                ? g_q[(size_t)(nbase + nn) * EE + g * DD + kk] : 0.f;
        }
        {
            const float* kv0 = g_kv + (((size_t)b * GG + g) * DD * DD);
            const float* kv1 = g_kv
                + ((((size_t)NGRAPH + b) * GG + g) * DD * DD);
            for (int i = tid; i < DD * DD; i += 256)
                (&Ks[0][0])[i] = (kv0[i] + kv1[i]) * inv;
        }
        __syncthreads();

        float acc[4][4];
#pragma unroll
        for (int i = 0; i < 4; i++)
#pragma unroll
            for (int j = 0; j < 4; j++) acc[i][j] = 0.f;

#pragma unroll
        for (int k = 0; k < DD; k++) {
            float ra[4], rb[4];
            *(float4*)ra = *(const float4*)&Qs[k][trow];
            *(float4*)rb = *(const float4*)&Ks[k][tcol];
#pragma unroll
            for (int i = 0; i < 4; i++)
#pragma unroll
                for (int j = 0; j < 4; j++)
                    acc[i][j] += ra[i] * rb[j];
        }

#pragma unroll
        for (int i = 0; i < 4; i++) {
            int r = trow + i;
            if (r < cnt) {
                size_t off = (size_t)(nbase + r) * EE + g * DD + tcol;
                __nv_bfloat16 h[4], l[4];
#pragma unroll
                for (int j = 0; j < 4; j++) {
                    h[j] = __float2bfloat16(acc[i][j]);
                    l[j] = __float2bfloat16(acc[i][j] - __bfloat162float(h[j]));
                }
                __nv_bfloat162 h01; h01.x = h[0]; h01.y = h[1];
                __nv_bfloat162 h23; h23.x = h[2]; h23.y = h[3];
                __nv_bfloat162 l01; l01.x = l[0]; l01.y = l[1];
                __nv_bfloat162 l23; l23.x = l[2]; l23.y = l[3];
                *(__nv_bfloat162*)(g_ah + off)     = h01;
                *(__nv_bfloat162*)(g_ah + off + 2) = h23;
                *(__nv_bfloat162*)(g_al + off)     = l01;
                *(__nv_bfloat162*)(g_al + off + 2) = l23;
            }
        }
    }
}

// ---------------------------------------------------------------------------
// Launch
// ---------------------------------------------------------------------------
extern "C" void kernel_launch(void* const* d_in, const int* in_sizes, int n_in,
                              void* d_out, int out_size)
{
    const float* x     = (const float*)d_in[0];
    const float* pos   = (const float*)d_in[1];
    const int*   batch = (const int*)d_in[2];
    const float* Wq    = (const float*)d_in[3];
    const float* bq    = (const float*)d_in[4];
    const float* Wv    = (const float*)d_in[5];
    const float* bv    = (const float*)d_in[6];
    const float* Wo    = (const float*)d_in[7];
    const float* bo    = (const float*)d_in[8];
    const float* freqs = (const float*)d_in[9];
    float* out = (float*)d_out;

    float *gq, *gv, *gk, *gbqv;
    __nv_bfloat16 *gxh, *gxl, *gah, *gal, *gwqvh, *gwqvl, *gwoh, *gwol;
    cudaGetSymbolAddress((void**)&gq, g_q);
    cudaGetSymbolAddress((void**)&gv, g_v);
    cudaGetSymbolAddress((void**)&gk, g_k);
    cudaGetSymbolAddress((void**)&gbqv, g_bqv);
    cudaGetSymbolAddress((void**)&gxh, g_xh);
    cudaGetSymbolAddress((void**)&gxl, g_xl);
    cudaGetSymbolAddress((void**)&gah, g_ah);
    cudaGetSymbolAddress((void**)&gal, g_al);
    cudaGetSymbolAddress((void**)&gwqvh, g_wqvh);
    cudaGetSymbolAddress((void**)&gwqvl, g_wqvl);
    cudaGetSymbolAddress((void**)&gwoh, g_woh);
    cudaGetSymbolAddress((void**)&gwol, g_wol);

    cudaFuncSetAttribute(gemm_mma,
                         cudaFuncAttributeMaxDynamicSharedMemorySize, GEMM_SMEM);

    // 1) bf16 hi/lo conversion; weight transpose+split
    convert_x_kernel<<<(NN * CCH / 4 + 255) / 256, 256>>>(x);
    prep_w_kernel<<<(NQV * CCH + CCH * EE + 255) / 256, 256>>>(Wq, Wv, Wo, bq, bv);

    // 2) fused QV projection + RoPE epilogue -> g_q (rot), g_k (rot ones), g_v
    gemm_mma<<<dim3(NQV / 128, NN / 128), 256, GEMM_SMEM>>>(
        gxh, gxl, gwqvh, gwqvl, gbqv, gq, gv, gk, pos, freqs, CCH, 1);

    // 3) kv = segsum(k outer v) per node-split (raw; summed+scaled at use)
    kv_kernel<<<dim3(GG * KVSPLIT, NGRAPH), 256>>>(batch);

    // 4) attn = q . kv[batch]/512 -> bf16 hi/lo
    attn_kernel<<<dim3(16, NGRAPH), 256>>>(batch);

    // 5) out = attn @ Wo + bo
    gemm_mma<<<dim3(EE / 128, NN / 128), 256, GEMM_SMEM>>>(
        gah, gal, gwoh, gwol, bo, out, out, nullptr, nullptr, nullptr, EE, 0);
}

// round 7
// speedup vs baseline: 2.1807x; 1.0927x over previous
#include <cuda_runtime.h>
#include <cuda_bf16.h>
#include <cstdint>
#include <cstddef>

// Problem constants
#define NN 32768
#define CCH 384
#define EE 384
#define GG 12
#define DD 32
#define PPAIR 16
#define NGRAPH 64
#define NQV 768

#define SW64(off) ((off) ^ (((off) >> 3) & 0x30))

// ---------------------------------------------------------------------------
// Scratch
// ---------------------------------------------------------------------------
#define KVSPLIT 4
__device__ float g_q[(size_t)NN * EE];
__device__ float g_v[(size_t)NN * EE];
__device__ float g_k[(size_t)NN * EE];
__device__ float g_kv[(size_t)KVSPLIT * NGRAPH * GG * DD * DD];
__device__ __nv_bfloat16 g_xh[(size_t)NN * CCH];
__device__ __nv_bfloat16 g_xl[(size_t)NN * CCH];
__device__ __nv_bfloat16 g_ah[(size_t)NN * EE];
__device__ __nv_bfloat16 g_al[(size_t)NN * EE];
__device__ __nv_bfloat16 g_wqvh[(size_t)NQV * CCH];
__device__ __nv_bfloat16 g_wqvl[(size_t)NQV * CCH];
__device__ __nv_bfloat16 g_woh[(size_t)CCH * EE];
__device__ __nv_bfloat16 g_wol[(size_t)CCH * EE];
__device__ float g_bqv[NQV];

// ---------------------------------------------------------------------------
// PTX wrappers (sm_80-baseline only)
// ---------------------------------------------------------------------------
__device__ __forceinline__ uint32_t smem_u32(const void* p) {
    uint32_t a;
    asm("{ .reg .u64 t; cvta.to.shared.u64 t, %1; cvt.u32.u64 %0, t; }"
        : "=r"(a) : "l"(p));
    return a;
}
__device__ __forceinline__ void cp_async16(uint32_t dst, const void* src) {
    asm volatile("cp.async.cg.shared.global [%0], [%1], 16;"
                 :: "r"(dst), "l"(src));
}
__device__ __forceinline__ void cp_commit() {
    asm volatile("cp.async.commit_group;");
}
__device__ __forceinline__ void cp_wait2() {
    asm volatile("cp.async.wait_group 2;");
}
__device__ __forceinline__ void cp_wait1() {
    asm volatile("cp.async.wait_group 1;");
}
__device__ __forceinline__ void cp_wait0() {
    asm volatile("cp.async.wait_group 0;");
}
__device__ __forceinline__ void ldm4(uint32_t* r, uint32_t addr) {
    asm volatile("ldmatrix.sync.aligned.m8n8.x4.shared.b16 {%0,%1,%2,%3}, [%4];"
                 : "=r"(r[0]), "=r"(r[1]), "=r"(r[2]), "=r"(r[3]) : "r"(addr));
}
__device__ __forceinline__ void mma_bf16(float* c, const uint32_t* a,
                                         const uint32_t b0, const uint32_t b1) {
    asm volatile(
        "mma.sync.aligned.m16n8k16.row.col.f32.bf16.bf16.f32 "
        "{%0,%1,%2,%3}, {%4,%5,%6,%7}, {%8,%9}, {%0,%1,%2,%3};"
        : "+f"(c[0]), "+f"(c[1]), "+f"(c[2]), "+f"(c[3])
        : "r"(a[0]), "r"(a[1]), "r"(a[2]), "r"(a[3]), "r"(b0), "r"(b1));
}

// ---------------------------------------------------------------------------
// Pipelined bf16x2 tensor GEMM, 128x128 tile, BK=32 (64B rows, SW64),
// 3-stage cp.async, 2 CTAs/SM. D = Ah*Bh + Al*Bh + Ah*Bl (fp32 accum).
// mode 1 = QV projection with RoPE fused into Q-half epilogue.
// ---------------------------------------------------------------------------
#define STAGE_BYTES 32768
#define NSTAGE 3
#define GEMM_SMEM (NSTAGE * STAGE_BYTES)

__global__ __launch_bounds__(256, 2) void gemm_mma(
    const __nv_bfloat16* __restrict__ Ah, const __nv_bfloat16* __restrict__ Al,
    const __nv_bfloat16* __restrict__ Bh, const __nv_bfloat16* __restrict__ Bl,
    const float* __restrict__ bias, float* __restrict__ outQ,
    float* __restrict__ outV, float* __restrict__ outK,
    const float* __restrict__ pos, const float* __restrict__ freqs,
    int kTot, int mode)
{
    extern __shared__ char smem[];
    const uint32_t uS = smem_u32(smem);

    const int tid = threadIdx.x;
    const int bm = blockIdx.y * 128;
    const int bn = blockIdx.x * 128;

    const int lrow = tid >> 1;
    const int lc = (tid & 1) * 2;
    const char* gA_h = (const char*)(Ah + (size_t)(bm + lrow) * kTot);
    const char* gA_l = (const char*)(Al + (size_t)(bm + lrow) * kTot);
    const char* gB_h = (const char*)(Bh + (size_t)(bn + lrow) * kTot);
    const char* gB_l = (const char*)(Bl + (size_t)(bn + lrow) * kTot);
    uint32_t sw[2];
#pragma unroll
    for (int i = 0; i < 2; i++)
        sw[i] = SW64((uint32_t)lrow * 64 + (lc + i) * 16);

    const int wid = tid >> 5, lane = tid & 31;
    const int wm = (wid & 3) * 32;
    const int wn = (wid >> 2) * 64;

    const uint32_t aRowOff = (uint32_t)(wm + (lane & 15)) * 64;
    const uint32_t aByte = (uint32_t)(lane >> 4) * 16;
    const uint32_t bRowOff =
        (uint32_t)(wn + ((lane >> 4) << 3) + (lane & 7)) * 64;
    const uint32_t bByte = (uint32_t)((lane >> 3) & 1) * 16;

    float acc[2][8][4];
#pragma unroll
    for (int mt = 0; mt < 2; mt++)
#pragma unroll
        for (int nt = 0; nt < 8; nt++)
#pragma unroll
            for (int j = 0; j < 4; j++) acc[mt][nt][j] = 0.f;

    const int nIter = kTot / 32;

    // prologue: stages 0 and 1
#pragma unroll
    for (int s = 0; s < 2; s++) {
        const uint32_t sb = uS + s * STAGE_BYTES;
        const int k0b = s * 64;
#pragma unroll
        for (int i = 0; i < 2; i++) {
            const int go = k0b + (lc + i) * 16;
            cp_async16(sb + sw[i], gA_h + go);
            cp_async16(sb + 8192 + sw[i], gA_l + go);
            cp_async16(sb + 16384 + sw[i], gB_h + go);
            cp_async16(sb + 24576 + sw[i], gB_l + go);
        }
        cp_commit();
    }

    int st = 0, ld = 2;
    for (int c = 0; c < nIter; c++) {
        if (c + 2 < nIter) {
            const uint32_t sb = uS + ld * STAGE_BYTES;
            const int k0b = (c + 2) * 64;
#pragma unroll
            for (int i = 0; i < 2; i++) {
                const int go = k0b + (lc + i) * 16;
                cp_async16(sb + sw[i], gA_h + go);
                cp_async16(sb + 8192 + sw[i], gA_l + go);
                cp_async16(sb + 16384 + sw[i], gB_h + go);
                cp_async16(sb + 24576 + sw[i], gB_l + go);
            }
            cp_commit();
            cp_wait2();
        } else if (c + 1 < nIter) {
            cp_wait1();
        } else {
            cp_wait0();
        }
        __syncthreads();

        const uint32_t base = uS + st * STAGE_BYTES;
        const uint32_t uAh = base, uAl = base + 8192;
        const uint32_t uBh = base + 16384, uBl = base + 24576;

#pragma unroll
        for (int ks = 0; ks < 2; ks++) {
            const uint32_t kb = (uint32_t)ks * 32;
            uint32_t ax[2][4], alx[2][4], bx[4][4];
#pragma unroll
            for (int mt = 0; mt < 2; mt++)
                ldm4(ax[mt], uAh + SW64(aRowOff + mt * 1024 + kb + aByte));
#pragma unroll
            for (int nt2 = 0; nt2 < 4; nt2++)
                ldm4(bx[nt2], uBh + SW64(bRowOff + nt2 * 1024 + kb + bByte));
#pragma unroll
            for (int mt = 0; mt < 2; mt++)
#pragma unroll
                for (int nt = 0; nt < 8; nt++)
                    mma_bf16(acc[mt][nt], ax[mt],
                             bx[nt >> 1][(nt & 1) * 2], bx[nt >> 1][(nt & 1) * 2 + 1]);
#pragma unroll
            for (int mt = 0; mt < 2; mt++)
                ldm4(alx[mt], uAl + SW64(aRowOff + mt * 1024 + kb + aByte));
#pragma unroll
            for (int mt = 0; mt < 2; mt++)
#pragma unroll
                for (int nt = 0; nt < 8; nt++)
                    mma_bf16(acc[mt][nt], alx[mt],
                             bx[nt >> 1][(nt & 1) * 2], bx[nt >> 1][(nt & 1) * 2 + 1]);
#pragma unroll
            for (int nt2 = 0; nt2 < 4; nt2++)
                ldm4(bx[nt2], uBl + SW64(bRowOff + nt2 * 1024 + kb + bByte));
#pragma unroll
            for (int mt = 0; mt < 2; mt++)
#pragma unroll
                for (int nt = 0; nt < 8; nt++)
                    mma_bf16(acc[mt][nt], ax[mt],
                             bx[nt >> 1][(nt & 1) * 2], bx[nt >> 1][(nt & 1) * 2 + 1]);
        }
        __syncthreads();
        st = (st == NSTAGE - 1) ? 0 : st + 1;
        ld = (ld == NSTAGE - 1) ? 0 : ld + 1;
    }

    // ------------------------- epilogue -------------------------
    const int r0 = bm + wm + (lane >> 2);
    const int cb = wn + (lane & 3) * 2;

    if (mode == 1 && bn < EE) {
        float px[4], py[4], pz[4];
        int rr[4];
#pragma unroll
        for (int j = 0; j < 4; j++) {
            rr[j] = r0 + (j >> 1) * 16 + (j & 1) * 8;
            px[j] = pos[rr[j] * 3 + 0];
            py[j] = pos[rr[j] * 3 + 1];
            pz[j] = pos[rr[j] * 3 + 2];
        }
#pragma unroll
        for (int nt = 0; nt < 8; nt++) {
            const int gc = bn + cb + nt * 8;          // even global column
            const int g = gc >> 5;
            const int p = (gc & 31) >> 1;
            const float* f = freqs + ((size_t)g * PPAIR + p) * 3;
            const float fx = f[0], fy = f[1], fz = f[2];
            const float b0 = bias[gc], b1 = bias[gc + 1];
#pragma unroll
            for (int mt = 0; mt < 2; mt++) {
#pragma unroll
                for (int h = 0; h < 2; h++) {
                    const int j = mt * 2 + h;
                    const float ph = px[j] * fx + py[j] * fy + pz[j] * fz;
                    const float sn = __sinf(ph);
                    const float cs = __cosf(ph);
                    const float x1 = acc[mt][nt][h * 2 + 0] + b0;
                    const float x2 = acc[mt][nt][h * 2 + 1] + b1;
                    float2 qv, kv;
                    qv.x = x1 * cs - x2 * sn;
                    qv.y = x1 * sn + x2 * cs;
                    kv.x = cs - sn;
                    kv.y = sn + cs;
                    const size_t o = (size_t)rr[j] * EE + gc;
                    *(float2*)&outQ[o] = qv;
                    *(float2*)&outK[o] = kv;
                }
            }
        }
    } else {
        float* dst = (mode == 1) ? outV : outQ;
        const int bcol = (mode == 1) ? bn - EE : bn;
#pragma unroll
        for (int mt = 0; mt < 2; mt++) {
            const int row = r0 + mt * 16;
#pragma unroll
            for (int nt = 0; nt < 8; nt++) {
                const int col = cb + nt * 8;
                const float b0 = bias[bn + col];
                const float b1 = bias[bn + col + 1];
                float2 v0, v1;
                v0.x = acc[mt][nt][0] + b0; v0.y = acc[mt][nt][1] + b1;
                v1.x = acc[mt][nt][2] + b0; v1.y = acc[mt][nt][3] + b1;
                *(float2*)&dst[(size_t)row * EE + bcol + col]       = v0;
                *(float2*)&dst[(size_t)(row + 8) * EE + bcol + col] = v1;
            }
        }
    }
}

// ---------------------------------------------------------------------------
// x -> bf16 hi/lo split
// ---------------------------------------------------------------------------
__global__ void convert_x_kernel(const float* __restrict__ x)
{
    int i = (blockIdx.x * blockDim.x + threadIdx.x) * 4;
    if (i >= NN * CCH) return;
    float4 v = *(const float4*)(x + i);
    float vv[4] = {v.x, v.y, v.z, v.w};
    __nv_bfloat16 h[4], l[4];
#pragma unroll
    for (int j = 0; j < 4; j++) {
        h[j] = __float2bfloat16(vv[j]);
        l[j] = __float2bfloat16(vv[j] - __bfloat162float(h[j]));
    }
    __nv_bfloat162 h01; h01.x = h[0]; h01.y = h[1];
    __nv_bfloat162 h23; h23.x = h[2]; h23.y = h[3];
    __nv_bfloat162 l01; l01.x = l[0]; l01.y = l[1];
    __nv_bfloat162 l23; l23.x = l[2]; l23.y = l[3];
    *(__nv_bfloat162*)(g_xh + i)     = h01;
    *(__nv_bfloat162*)(g_xh + i + 2) = h23;
    *(__nv_bfloat162*)(g_xl + i)     = l01;
    *(__nv_bfloat162*)(g_xl + i + 2) = l23;
}

// ---------------------------------------------------------------------------
// Transpose + split weights
// ---------------------------------------------------------------------------
__global__ void prep_w_kernel(const float* __restrict__ Wq,
                              const float* __restrict__ Wv,
                              const float* __restrict__ Wo,
                              const float* __restrict__ bq,
                              const float* __restrict__ bv)
{
    int idx = blockIdx.x * blockDim.x + threadIdx.x;
    const int T1 = NQV * CCH;
    if (idx < T1) {
        int n = idx / CCH, k = idx % CCH;
        float f = (n < EE) ? Wq[(size_t)k * EE + n] : Wv[(size_t)k * EE + (n - EE)];
        __nv_bfloat16 h = __float2bfloat16(f);
        g_wqvh[idx] = h;
        g_wqvl[idx] = __float2bfloat16(f - __bfloat162float(h));
    } else if (idx < T1 + CCH * EE) {
        int j = idx - T1;
        int n = j / EE, k = j % EE;
        float f = Wo[(size_t)k * CCH + n];
        __nv_bfloat16 h = __float2bfloat16(f);
        g_woh[j] = h;
        g_wol[j] = __float2bfloat16(f - __bfloat162float(h));
    }
    if (idx < NQV) g_bqv[idx] = (idx < EE) ? bq[idx] : bv[idx - EE];
}

// ---------------------------------------------------------------------------
// Inline segment bound (batch is sorted)
// ---------------------------------------------------------------------------
__device__ __forceinline__ int seg_lower(const int* __restrict__ batch, int t)
{
    int lo = 0, hi = NN;
    while (lo < hi) {
        int mid = (lo + hi) >> 1;
        if (batch[mid] < t) lo = mid + 1; else hi = mid;
    }
    return lo;
}

// ---------------------------------------------------------------------------
// KV segment reduction, v4: 4x4 per-thread microtile.
// Block = (group-tile gt of 4 groups, node-split sp, graph b), 256 threads:
// thread (gq, d4, e4) accumulates kv[gt*4+gq][d4..d4+3][e4..e4+3].
// cp.async double-buffered 16-node chunks of 4-group-wide k/v slices.
// ---------------------------------------------------------------------------
#define KVCH 16
__global__ __launch_bounds__(256) void kv_kernel(const int* __restrict__ batch)
{
    const int bx = blockIdx.x;
    const int gt = bx % 3;             // group tile: groups gt*4 .. gt*4+3
    const int sp = bx / 3;             // node split 0..3
    const int b = blockIdx.y;
    const int s = seg_lower(batch, b);
    const int e = seg_lower(batch, b + 1);
    const int len = e - s;
    const int per = (len + KVSPLIT - 1) / KVSPLIT;
    const int rs = s + sp * per;
    const int re = min(e, rs + per);

    const int tid = threadIdx.x;
    const int gq = tid >> 6;           // 0..3 local group
    const int t64 = tid & 63;
    const int d4 = ((t64 >> 3) & 7) * 4;  // 0..28
    const int e4 = (t64 & 7) * 4;         // 0..28
    const int g = gt * 4 + gq;
    const int cbase = gq * DD;

    __shared__ float sk[2][KVCH][128];
    __shared__ float sv[2][KVCH][128];

    // loader mapping: 1024 float4 per (stage, chunk) -> 4 per thread
    // i = tid + j*256; arr = i>=512; r = i & 511; node = r>>5; c4 = r&31
    const float* __restrict__ karr = g_k;
    const float* __restrict__ varr = g_v;

    float acc[4][4];
#pragma unroll
    for (int i = 0; i < 4; i++)
#pragma unroll
        for (int j = 0; j < 4; j++) acc[i][j] = 0.f;

    if (rs < re) {
        const int gcol = gt * 128;     // float offset of this 4-group slice

        // prologue: stage 0
#pragma unroll
        for (int j = 0; j < 4; j++) {
            const int i = tid + j * 256;
            const int arr = i >> 9;
            const int r = i & 511;
            const int node = r >> 5;
            const int c4 = r & 31;
            if (rs + node < re) {
                const float* src = (arr ? varr : karr)
                    + (size_t)(rs + node) * CCH + gcol + c4 * 4;
                const uint32_t dst = smem_u32(
                    arr ? &sv[0][node][c4 * 4] : &sk[0][node][c4 * 4]);
                cp_async16(dst, src);
            }
        }
        cp_commit();

        int st = 0;
        for (int n0 = rs; n0 < re; n0 += KVCH, st ^= 1) {
            const int nn = n0 + KVCH;
            if (nn < re) {
                const int nst = st ^ 1;
#pragma unroll
                for (int j = 0; j < 4; j++) {
                    const int i = tid + j * 256;
                    const int arr = i >> 9;
                    const int r = i & 511;
                    const int node = r >> 5;
                    const int c4 = r & 31;
                    if (nn + node < re) {
                        const float* src = (arr ? varr : karr)
                            + (size_t)(nn + node) * CCH + gcol + c4 * 4;
                        const uint32_t dst = smem_u32(
                            arr ? &sv[nst][node][c4 * 4] : &sk[nst][node][c4 * 4]);
                        cp_async16(dst, src);
                    }
                }
                cp_commit();
                cp_wait1();
            } else {
                cp_wait0();
            }
            __syncthreads();
            const int cnt = min(KVCH, re - n0);
            for (int c = 0; c < cnt; c++) {
                const float4 kk = *(const float4*)&sk[st][c][cbase + d4];
                const float4 vv = *(const float4*)&sv[st][c][cbase + e4];
                acc[0][0] += kk.x * vv.x; acc[0][1] += kk.x * vv.y;
                acc[0][2] += kk.x * vv.z; acc[0][3] += kk.x * vv.w;
                acc[1][0] += kk.y * vv.x; acc[1][1] += kk.y * vv.y;
                acc[1][2] += kk.y * vv.z; acc[1][3] += kk.y * vv.w;
                acc[2][0] += kk.z * vv.x; acc[2][1] += kk.z * vv.y;
                acc[2][2] += kk.z * vv.z; acc[2][3] += kk.z * vv.w;
                acc[3][0] += kk.w * vv.x; acc[3][1] += kk.w * vv.y;
                acc[3][2] += kk.w * vv.z; acc[3][3] += kk.w * vv.w;
            }
            __syncthreads();
        }
    }

    float* dst = g_kv
        + ((((size_t)sp * NGRAPH + b) * GG + g) * DD + d4) * DD + e4;
#pragma unroll
    for (int i = 0; i < 4; i++) {
        float4 o;
        o.x = acc[i][0]; o.y = acc[i][1]; o.z = acc[i][2]; o.w = acc[i][3];
        *(float4*)(dst + (size_t)i * DD) = o;
    }
}

// ---------------------------------------------------------------------------
// Apply: attn = q . kv[batch] (sums the 4 split buffers, scales by 1/512);
// emits bf16 hi/lo for the final GEMM
// ---------------------------------------------------------------------------
#define ACH 128
__global__ __launch_bounds__(256) void attn_kernel(const int* __restrict__ batch)
{
    int c = blockIdx.x;
    int b = blockIdx.y;
    int s = seg_lower(batch, b);
    int e = seg_lower(batch, b + 1);
    int nbase = s + c * ACH;
    if (nbase >= e) return;
    int cnt = min(ACH, e - nbase);
    int tid = threadIdx.x;

    __shared__ float Qs[DD][ACH + 4];
    __shared__ float Ks[DD][DD];

    int trow = (tid >> 3) * 4;
    int tcol = (tid & 7) * 4;

    const float inv = 1.0f / 512.0f;
    const size_t spStride = (size_t)NGRAPH * GG * DD * DD;

    for (int g = 0; g < GG; g++) {
        __syncthreads();
        for (int i = tid; i < ACH * DD; i += 256) {
            int nn = i >> 5, kk = i & 31;
            Qs[kk][nn] = (nn < cnt)
                ? g_q[(size_t)(nbase + nn) * EE + g * DD + kk] : 0.f;
        }
        {
            const float* kvp = g_kv + (((size_t)b * GG + g) * DD * DD);
            for (int i = tid; i < DD * DD; i += 256) {
                float sum = kvp[i] + kvp[i + spStride]
                          + kvp[i + 2 * spStride] + kvp[i + 3 * spStride];
                (&Ks[0][0])[i] = sum * inv;
            }
        }
        __syncthreads();

        float acc[4][4];
#pragma unroll
        for (int i = 0; i < 4; i++)
#pragma unroll
            for (int j = 0; j < 4; j++) acc[i][j] = 0.f;

#pragma unroll
        for (int k = 0; k < DD; k++) {
            float ra[4], rb[4];
            *(float4*)ra = *(const float4*)&Qs[k][trow];
            *(float4*)rb = *(const float4*)&Ks[k][tcol];
#pragma unroll
            for (int i = 0; i < 4; i++)
#pragma unroll
                for (int j = 0; j < 4; j++)
                    acc[i][j] += ra[i] * rb[j];
        }

#pragma unroll
        for (int i = 0; i < 4; i++) {
            int r = trow + i;
            if (r < cnt) {
                size_t off = (size_t)(nbase + r) * EE + g * DD + tcol;
                __nv_bfloat16 h[4], l[4];
#pragma unroll
                for (int j = 0; j < 4; j++) {
                    h[j] = __float2bfloat16(acc[i][j]);
                    l[j] = __float2bfloat16(acc[i][j] - __bfloat162float(h[j]));
                }
                __nv_bfloat162 h01; h01.x = h[0]; h01.y = h[1];
                __nv_bfloat162 h23; h23.x = h[2]; h23.y = h[3];
                __nv_bfloat162 l01; l01.x = l[0]; l01.y = l[1];
                __nv_bfloat162 l23; l23.x = l[2]; l23.y = l[3];
                *(__nv_bfloat162*)(g_ah + off)     = h01;
                *(__nv_bfloat162*)(g_ah + off + 2) = h23;
                *(__nv_bfloat162*)(g_al + off)     = l01;
                *(__nv_bfloat162*)(g_al + off + 2) = l23;
            }
        }
    }
}

// ---------------------------------------------------------------------------
// Launch
// ---------------------------------------------------------------------------
extern "C" void kernel_launch(void* const* d_in, const int* in_sizes, int n_in,
                              void* d_out, int out_size)
{
    const float* x     = (const float*)d_in[0];
    const float* pos   = (const float*)d_in[1];
    const int*   batch = (const int*)d_in[2];
    const float* Wq    = (const float*)d_in[3];
    const float* bq    = (const float*)d_in[4];
    const float* Wv    = (const float*)d_in[5];
    const float* bv    = (const float*)d_in[6];
    const float* Wo    = (const float*)d_in[7];
    const float* bo    = (const float*)d_in[8];
    const float* freqs = (const float*)d_in[9];
    float* out = (float*)d_out;

    float *gq, *gv, *gk, *gbqv;
    __nv_bfloat16 *gxh, *gxl, *gah, *gal, *gwqvh, *gwqvl, *gwoh, *gwol;
    cudaGetSymbolAddress((void**)&gq, g_q);
    cudaGetSymbolAddress((void**)&gv, g_v);
    cudaGetSymbolAddress((void**)&gk, g_k);
    cudaGetSymbolAddress((void**)&gbqv, g_bqv);
    cudaGetSymbolAddress((void**)&gxh, g_xh);
    cudaGetSymbolAddress((void**)&gxl, g_xl);
    cudaGetSymbolAddress((void**)&gah, g_ah);
    cudaGetSymbolAddress((void**)&gal, g_al);
    cudaGetSymbolAddress((void**)&gwqvh, g_wqvh);
    cudaGetSymbolAddress((void**)&gwqvl, g_wqvl);
    cudaGetSymbolAddress((void**)&gwoh, g_woh);
    cudaGetSymbolAddress((void**)&gwol, g_wol);

    cudaFuncSetAttribute(gemm_mma,
                         cudaFuncAttributeMaxDynamicSharedMemorySize, GEMM_SMEM);

    // 1) bf16 hi/lo conversion; weight transpose+split
    convert_x_kernel<<<(NN * CCH / 4 + 255) / 256, 256>>>(x);
    prep_w_kernel<<<(NQV * CCH + CCH * EE + 255) / 256, 256>>>(Wq, Wv, Wo, bq, bv);

    // 2) fused QV projection + RoPE epilogue -> g_q (rot), g_k (rot ones), g_v
    gemm_mma<<<dim3(NQV / 128, NN / 128), 256, GEMM_SMEM>>>(
        gxh, gxl, gwqvh, gwqvl, gbqv, gq, gv, gk, pos, freqs, CCH, 1);

    // 3) kv = segsum(k outer v) per node-split (raw; summed+scaled at use)
    kv_kernel<<<dim3(3 * KVSPLIT, NGRAPH), 256>>>(batch);

    // 4) attn = q . kv[batch]/512 -> bf16 hi/lo
    attn_kernel<<<dim3(16, NGRAPH), 256>>>(batch);

    // 5) out = attn @ Wo + bo
    gemm_mma<<<dim3(EE / 128, NN / 128), 256, GEMM_SMEM>>>(
        gah, gal, gwoh, gwol, bo, out, out, nullptr, nullptr, nullptr, EE, 0);
}

// round 8
// speedup vs baseline: 2.6554x; 1.2177x over previous
#include <cuda_runtime.h>
#include <cuda_fp16.h>
#include <cstdint>
#include <cstddef>

// Problem constants
#define NN 32768
#define CCH 384
#define EE 384
#define GG 12
#define DD 32
#define PPAIR 16
#define NGRAPH 64
#define NQV 768

#define SW64(off) ((off) ^ (((off) >> 3) & 0x30))

// ---------------------------------------------------------------------------
// Scratch
// ---------------------------------------------------------------------------
#define KVSPLIT 4
__device__ float g_q[(size_t)NN * EE];
__device__ float g_v[(size_t)NN * EE];
__device__ float g_k[(size_t)NN * EE];
__device__ float g_kv[(size_t)KVSPLIT * NGRAPH * GG * DD * DD];
__device__ __half g_xh[(size_t)NN * CCH];
__device__ __half g_xl[(size_t)NN * CCH];
__device__ __half g_ah[(size_t)NN * EE];
__device__ __half g_al[(size_t)NN * EE];
__device__ __half g_wqvh[(size_t)NQV * CCH];
__device__ __half g_woh[(size_t)CCH * EE];
__device__ float g_bqv[NQV];

// ---------------------------------------------------------------------------
// PTX wrappers (sm_80-baseline only)
// ---------------------------------------------------------------------------
__device__ __forceinline__ uint32_t smem_u32(const void* p) {
    uint32_t a;
    asm("{ .reg .u64 t; cvta.to.shared.u64 t, %1; cvt.u32.u64 %0, t; }"
        : "=r"(a) : "l"(p));
    return a;
}
__device__ __forceinline__ void cp_async16(uint32_t dst, const void* src) {
    asm volatile("cp.async.cg.shared.global [%0], [%1], 16;"
                 :: "r"(dst), "l"(src));
}
__device__ __forceinline__ void cp_commit() {
    asm volatile("cp.async.commit_group;");
}
__device__ __forceinline__ void cp_wait3() {
    asm volatile("cp.async.wait_group 3;");
}
__device__ __forceinline__ void cp_wait2() {
    asm volatile("cp.async.wait_group 2;");
}
__device__ __forceinline__ void cp_wait1() {
    asm volatile("cp.async.wait_group 1;");
}
__device__ __forceinline__ void cp_wait0() {
    asm volatile("cp.async.wait_group 0;");
}
__device__ __forceinline__ void ldm4(uint32_t* r, uint32_t addr) {
    asm volatile("ldmatrix.sync.aligned.m8n8.x4.shared.b16 {%0,%1,%2,%3}, [%4];"
                 : "=r"(r[0]), "=r"(r[1]), "=r"(r[2]), "=r"(r[3]) : "r"(addr));
}
__device__ __forceinline__ void mma_f16(float* c, const uint32_t* a,
                                        const uint32_t b0, const uint32_t b1) {
    asm volatile(
        "mma.sync.aligned.m16n8k16.row.col.f32.f16.f16.f32 "
        "{%0,%1,%2,%3}, {%4,%5,%6,%7}, {%8,%9}, {%0,%1,%2,%3};"
        : "+f"(c[0]), "+f"(c[1]), "+f"(c[2]), "+f"(c[3])
        : "r"(a[0]), "r"(a[1]), "r"(a[2]), "r"(a[3]), "r"(b0), "r"(b1));
}

// ---------------------------------------------------------------------------
// Pipelined fp16x2 tensor GEMM, 128x128 tile, BK=32 (64B rows, SW64),
// 4-stage cp.async, 24KB/stage -> 96KB -> 2 CTAs/SM.
// D = Ah*Bh + Al*Bh (fp32 accum; A split to 22 mantissa bits, B fp16).
// mode 1 = QV projection with RoPE fused into Q-half epilogue.
// ---------------------------------------------------------------------------
#define STAGE_BYTES 24576
#define NSTAGE 4
#define GEMM_SMEM (NSTAGE * STAGE_BYTES)

__global__ __launch_bounds__(256, 2) void gemm_mma(
    const __half* __restrict__ Ah, const __half* __restrict__ Al,
    const __half* __restrict__ Bh,
    const float* __restrict__ bias, float* __restrict__ outQ,
    float* __restrict__ outV, float* __restrict__ outK,
    const float* __restrict__ pos, const float* __restrict__ freqs,
    int kTot, int mode)
{
    extern __shared__ char smem[];
    const uint32_t uS = smem_u32(smem);

    const int tid = threadIdx.x;
    const int bm = blockIdx.y * 128;
    const int bn = blockIdx.x * 128;

    const int lrow = tid >> 1;
    const int lc = (tid & 1) * 2;
    const char* gA_h = (const char*)(Ah + (size_t)(bm + lrow) * kTot);
    const char* gA_l = (const char*)(Al + (size_t)(bm + lrow) * kTot);
    const char* gB_h = (const char*)(Bh + (size_t)(bn + lrow) * kTot);
    uint32_t sw[2];
#pragma unroll
    for (int i = 0; i < 2; i++)
        sw[i] = SW64((uint32_t)lrow * 64 + (lc + i) * 16);

    const int wid = tid >> 5, lane = tid & 31;
    const int wm = (wid & 3) * 32;
    const int wn = (wid >> 2) * 64;

    const uint32_t aRowOff = (uint32_t)(wm + (lane & 15)) * 64;
    const uint32_t aByte = (uint32_t)(lane >> 4) * 16;
    const uint32_t bRowOff =
        (uint32_t)(wn + ((lane >> 4) << 3) + (lane & 7)) * 64;
    const uint32_t bByte = (uint32_t)((lane >> 3) & 1) * 16;

    float acc[2][8][4];
#pragma unroll
    for (int mt = 0; mt < 2; mt++)
#pragma unroll
        for (int nt = 0; nt < 8; nt++)
#pragma unroll
            for (int j = 0; j < 4; j++) acc[mt][nt][j] = 0.f;

    const int nIter = kTot / 32;

    // prologue: stages 0..2
#pragma unroll
    for (int s = 0; s < 3; s++) {
        const uint32_t sb = uS + s * STAGE_BYTES;
        const int k0b = s * 64;
#pragma unroll
        for (int i = 0; i < 2; i++) {
            const int go = k0b + (lc + i) * 16;
            cp_async16(sb + sw[i], gA_h + go);
            cp_async16(sb + 8192 + sw[i], gA_l + go);
            cp_async16(sb + 16384 + sw[i], gB_h + go);
        }
        cp_commit();
    }

    int st = 0, ld = 3;
    for (int c = 0; c < nIter; c++) {
        if (c + 3 < nIter) {
            const uint32_t sb = uS + ld * STAGE_BYTES;
            const int k0b = (c + 3) * 64;
#pragma unroll
            for (int i = 0; i < 2; i++) {
                const int go = k0b + (lc + i) * 16;
                cp_async16(sb + sw[i], gA_h + go);
                cp_async16(sb + 8192 + sw[i], gA_l + go);
                cp_async16(sb + 16384 + sw[i], gB_h + go);
            }
            cp_commit();
            cp_wait3();
        } else {
            const int rem = nIter - 1 - c;
            if (rem == 2) cp_wait2();
            else if (rem == 1) cp_wait1();
            else cp_wait0();
        }
        __syncthreads();

        const uint32_t base = uS + st * STAGE_BYTES;
        const uint32_t uAh = base, uAl = base + 8192;
        const uint32_t uBh = base + 16384;

#pragma unroll
        for (int ks = 0; ks < 2; ks++) {
            const uint32_t kb = (uint32_t)ks * 32;
            uint32_t ax[2][4], alx[2][4], bx[4][4];
#pragma unroll
            for (int mt = 0; mt < 2; mt++)
                ldm4(ax[mt], uAh + SW64(aRowOff + mt * 1024 + kb + aByte));
#pragma unroll
            for (int nt2 = 0; nt2 < 4; nt2++)
                ldm4(bx[nt2], uBh + SW64(bRowOff + nt2 * 1024 + kb + bByte));
#pragma unroll
            for (int mt = 0; mt < 2; mt++)
#pragma unroll
                for (int nt = 0; nt < 8; nt++)
                    mma_f16(acc[mt][nt], ax[mt],
                            bx[nt >> 1][(nt & 1) * 2], bx[nt >> 1][(nt & 1) * 2 + 1]);
#pragma unroll
            for (int mt = 0; mt < 2; mt++)
                ldm4(alx[mt], uAl + SW64(aRowOff + mt * 1024 + kb + aByte));
#pragma unroll
            for (int mt = 0; mt < 2; mt++)
#pragma unroll
                for (int nt = 0; nt < 8; nt++)
                    mma_f16(acc[mt][nt], alx[mt],
                            bx[nt >> 1][(nt & 1) * 2], bx[nt >> 1][(nt & 1) * 2 + 1]);
        }
        __syncthreads();
        st = (st == NSTAGE - 1) ? 0 : st + 1;
        ld = (ld == NSTAGE - 1) ? 0 : ld + 1;
    }

    // ------------------------- epilogue -------------------------
    const int r0 = bm + wm + (lane >> 2);
    const int cb = wn + (lane & 3) * 2;

    if (mode == 1 && bn < EE) {
        float px[4], py[4], pz[4];
        int rr[4];
#pragma unroll
        for (int j = 0; j < 4; j++) {
            rr[j] = r0 + (j >> 1) * 16 + (j & 1) * 8;
            px[j] = pos[rr[j] * 3 + 0];
            py[j] = pos[rr[j] * 3 + 1];
            pz[j] = pos[rr[j] * 3 + 2];
        }
#pragma unroll
        for (int nt = 0; nt < 8; nt++) {
            const int gc = bn + cb + nt * 8;          // even global column
            const int g = gc >> 5;
            const int p = (gc & 31) >> 1;
            const float* f = freqs + ((size_t)g * PPAIR + p) * 3;
            const float fx = f[0], fy = f[1], fz = f[2];
            const float b0 = bias[gc], b1 = bias[gc + 1];
#pragma unroll
            for (int mt = 0; mt < 2; mt++) {
#pragma unroll
                for (int h = 0; h < 2; h++) {
                    const int j = mt * 2 + h;
                    const float ph = px[j] * fx + py[j] * fy + pz[j] * fz;
                    const float sn = __sinf(ph);
                    const float cs = __cosf(ph);
                    const float x1 = acc[mt][nt][h * 2 + 0] + b0;
                    const float x2 = acc[mt][nt][h * 2 + 1] + b1;
                    float2 qv, kv;
                    qv.x = x1 * cs - x2 * sn;
                    qv.y = x1 * sn + x2 * cs;
                    kv.x = cs - sn;
                    kv.y = sn + cs;
                    const size_t o = (size_t)rr[j] * EE + gc;
                    *(float2*)&outQ[o] = qv;
                    *(float2*)&outK[o] = kv;
                }
            }
        }
    } else {
        float* dst = (mode == 1) ? outV : outQ;
        const int bcol = (mode == 1) ? bn - EE : bn;
#pragma unroll
        for (int mt = 0; mt < 2; mt++) {
            const int row = r0 + mt * 16;
#pragma unroll
            for (int nt = 0; nt < 8; nt++) {
                const int col = cb + nt * 8;
                const float b0 = bias[bn + col];
                const float b1 = bias[bn + col + 1];
                float2 v0, v1;
                v0.x = acc[mt][nt][0] + b0; v0.y = acc[mt][nt][1] + b1;
                v1.x = acc[mt][nt][2] + b0; v1.y = acc[mt][nt][3] + b1;
                *(float2*)&dst[(size_t)row * EE + bcol + col]       = v0;
                *(float2*)&dst[(size_t)(row + 8) * EE + bcol + col] = v1;
            }
        }
    }
}

// ---------------------------------------------------------------------------
// x -> fp16 hi/lo split
// ---------------------------------------------------------------------------
__global__ void convert_x_kernel(const float* __restrict__ x)
{
    int i = (blockIdx.x * blockDim.x + threadIdx.x) * 4;
    if (i >= NN * CCH) return;
    float4 v = *(const float4*)(x + i);
    float vv[4] = {v.x, v.y, v.z, v.w};
    __half h[4], l[4];
#pragma unroll
    for (int j = 0; j < 4; j++) {
        h[j] = __float2half_rn(vv[j]);
        l[j] = __float2half_rn(vv[j] - __half2float(h[j]));
    }
    __half2 h01; h01.x = h[0]; h01.y = h[1];
    __half2 h23; h23.x = h[2]; h23.y = h[3];
    __half2 l01; l01.x = l[0]; l01.y = l[1];
    __half2 l23; l23.x = l[2]; l23.y = l[3];
    *(__half2*)(g_xh + i)     = h01;
    *(__half2*)(g_xh + i + 2) = h23;
    *(__half2*)(g_xl + i)     = l01;
    *(__half2*)(g_xl + i + 2) = l23;
}

// ---------------------------------------------------------------------------
// Transpose weights to fp16 (B side needs hi only)
// ---------------------------------------------------------------------------
__global__ void prep_w_kernel(const float* __restrict__ Wq,
                              const float* __restrict__ Wv,
                              const float* __restrict__ Wo,
                              const float* __restrict__ bq,
                              const float* __restrict__ bv)
{
    int idx = blockIdx.x * blockDim.x + threadIdx.x;
    const int T1 = NQV * CCH;
    if (idx < T1) {
        int n = idx / CCH, k = idx % CCH;
        float f = (n < EE) ? Wq[(size_t)k * EE + n] : Wv[(size_t)k * EE + (n - EE)];
        g_wqvh[idx] = __float2half_rn(f);
    } else if (idx < T1 + CCH * EE) {
        int j = idx - T1;
        int n = j / EE, k = j % EE;
        g_woh[j] = __float2half_rn(Wo[(size_t)k * CCH + n]);
    }
    if (idx < NQV) g_bqv[idx] = (idx < EE) ? bq[idx] : bv[idx - EE];
}

// ---------------------------------------------------------------------------
// Inline segment bound (batch is sorted)
// ---------------------------------------------------------------------------
__device__ __forceinline__ int seg_lower(const int* __restrict__ batch, int t)
{
    int lo = 0, hi = NN;
    while (lo < hi) {
        int mid = (lo + hi) >> 1;
        if (batch[mid] < t) lo = mid + 1; else hi = mid;
    }
    return lo;
}

// ---------------------------------------------------------------------------
// KV segment reduction, v4: 4x4 per-thread microtile (unchanged from R7).
// ---------------------------------------------------------------------------
#define KVCH 16
__global__ __launch_bounds__(256) void kv_kernel(const int* __restrict__ batch)
{
    const int bx = blockIdx.x;
    const int gt = bx % 3;
    const int sp = bx / 3;
    const int b = blockIdx.y;
    const int s = seg_lower(batch, b);
    const int e = seg_lower(batch, b + 1);
    const int len = e - s;
    const int per = (len + KVSPLIT - 1) / KVSPLIT;
    const int rs = s + sp * per;
    const int re = min(e, rs + per);

    const int tid = threadIdx.x;
    const int gq = tid >> 6;
    const int t64 = tid & 63;
    const int d4 = ((t64 >> 3) & 7) * 4;
    const int e4 = (t64 & 7) * 4;
    const int g = gt * 4 + gq;
    const int cbase = gq * DD;

    __shared__ float sk[2][KVCH][128];
    __shared__ float sv[2][KVCH][128];

    const float* __restrict__ karr = g_k;
    const float* __restrict__ varr = g_v;

    float acc[4][4];
#pragma unroll
    for (int i = 0; i < 4; i++)
#pragma unroll
        for (int j = 0; j < 4; j++) acc[i][j] = 0.f;

    if (rs < re) {
        const int gcol = gt * 128;

#pragma unroll
        for (int j = 0; j < 4; j++) {
            const int i = tid + j * 256;
            const int arr = i >> 9;
            const int r = i & 511;
            const int node = r >> 5;
            const int c4 = r & 31;
            if (rs + node < re) {
                const float* src = (arr ? varr : karr)
                    + (size_t)(rs + node) * CCH + gcol + c4 * 4;
                const uint32_t dst = smem_u32(
                    arr ? &sv[0][node][c4 * 4] : &sk[0][node][c4 * 4]);
                cp_async16(dst, src);
            }
        }
        cp_commit();

        int st = 0;
        for (int n0 = rs; n0 < re; n0 += KVCH, st ^= 1) {
            const int nn = n0 + KVCH;
            if (nn < re) {
                const int nst = st ^ 1;
#pragma unroll
                for (int j = 0; j < 4; j++) {
                    const int i = tid + j * 256;
                    const int arr = i >> 9;
                    const int r = i & 511;
                    const int node = r >> 5;
                    const int c4 = r & 31;
                    if (nn + node < re) {
                        const float* src = (arr ? varr : karr)
                            + (size_t)(nn + node) * CCH + gcol + c4 * 4;
                        const uint32_t dst = smem_u32(
                            arr ? &sv[nst][node][c4 * 4] : &sk[nst][node][c4 * 4]);
                        cp_async16(dst, src);
                    }
                }
                cp_commit();
                cp_wait1();
            } else {
                cp_wait0();
            }
            __syncthreads();
            const int cnt = min(KVCH, re - n0);
            for (int c = 0; c < cnt; c++) {
                const float4 kk = *(const float4*)&sk[st][c][cbase + d4];
                const float4 vv = *(const float4*)&sv[st][c][cbase + e4];
                acc[0][0] += kk.x * vv.x; acc[0][1] += kk.x * vv.y;
                acc[0][2] += kk.x * vv.z; acc[0][3] += kk.x * vv.w;
                acc[1][0] += kk.y * vv.x; acc[1][1] += kk.y * vv.y;
                acc[1][2] += kk.y * vv.z; acc[1][3] += kk.y * vv.w;
                acc[2][0] += kk.z * vv.x; acc[2][1] += kk.z * vv.y;
                acc[2][2] += kk.z * vv.z; acc[2][3] += kk.z * vv.w;
                acc[3][0] += kk.w * vv.x; acc[3][1] += kk.w * vv.y;
                acc[3][2] += kk.w * vv.z; acc[3][3] += kk.w * vv.w;
            }
            __syncthreads();
        }
    }

    float* dst = g_kv
        + ((((size_t)sp * NGRAPH + b) * GG + g) * DD + d4) * DD + e4;
#pragma unroll
    for (int i = 0; i < 4; i++) {
        float4 o;
        o.x = acc[i][0]; o.y = acc[i][1]; o.z = acc[i][2]; o.w = acc[i][3];
        *(float4*)(dst + (size_t)i * DD) = o;
    }
}

// ---------------------------------------------------------------------------
// Apply: attn = q . kv[batch] (sums 4 split buffers, scales by 1/512);
// emits fp16 hi/lo for the final GEMM
// ---------------------------------------------------------------------------
#define ACH 128
__global__ __launch_bounds__(256) void attn_kernel(const int* __restrict__ batch)
{
    int c = blockIdx.x;
    int b = blockIdx.y;
    int s = seg_lower(batch, b);
    int e = seg_lower(batch, b + 1);
    int nbase = s + c * ACH;
    if (nbase >= e) return;
    int cnt = min(ACH, e - nbase);
    int tid = threadIdx.x;

    __shared__ float Qs[DD][ACH + 4];
    __shared__ float Ks[DD][DD];

    int trow = (tid >> 3) * 4;
    int tcol = (tid & 7) * 4;

    const float inv = 1.0f / 512.0f;
    const size_t spStride = (size_t)NGRAPH * GG * DD * DD;

    for (int g = 0; g < GG; g++) {
        __syncthreads();
        for (int i = tid; i < ACH * DD; i += 256) {
            int nn = i >> 5, kk = i & 31;
            Qs[kk][nn] = (nn < cnt)
                ? g_q[(size_t)(nbase + nn) * EE + g * DD + kk] : 0.f;
        }
        {
            const float* kvp = g_kv + (((size_t)b * GG + g) * DD * DD);
            for (int i = tid; i < DD * DD; i += 256) {
                float sum = kvp[i] + kvp[i + spStride]
                          + kvp[i + 2 * spStride] + kvp[i + 3 * spStride];
                (&Ks[0][0])[i] = sum * inv;
            }
        }
        __syncthreads();

        float acc[4][4];
#pragma unroll
        for (int i = 0; i < 4; i++)
#pragma unroll
            for (int j = 0; j < 4; j++) acc[i][j] = 0.f;

#pragma unroll
        for (int k = 0; k < DD; k++) {
            float ra[4], rb[4];
            *(float4*)ra = *(const float4*)&Qs[k][trow];
            *(float4*)rb = *(const float4*)&Ks[k][tcol];
#pragma unroll
            for (int i = 0; i < 4; i++)
#pragma unroll
                for (int j = 0; j < 4; j++)
                    acc[i][j] += ra[i] * rb[j];
        }

#pragma unroll
        for (int i = 0; i < 4; i++) {
            int r = trow + i;
            if (r < cnt) {
                size_t off = (size_t)(nbase + r) * EE + g * DD + tcol;
                __half h[4], l[4];
#pragma unroll
                for (int j = 0; j < 4; j++) {
                    h[j] = __float2half_rn(acc[i][j]);
                    l[j] = __float2half_rn(acc[i][j] - __half2float(h[j]));
                }
                __half2 h01; h01.x = h[0]; h01.y = h[1];
                __half2 h23; h23.x = h[2]; h23.y = h[3];
                __half2 l01; l01.x = l[0]; l01.y = l[1];
                __half2 l23; l23.x = l[2]; l23.y = l[3];
                *(__half2*)(g_ah + off)     = h01;
                *(__half2*)(g_ah + off + 2) = h23;
                *(__half2*)(g_al + off)     = l01;
                *(__half2*)(g_al + off + 2) = l23;
            }
        }
    }
}

// ---------------------------------------------------------------------------
// Launch
// ---------------------------------------------------------------------------
extern "C" void kernel_launch(void* const* d_in, const int* in_sizes, int n_in,
                              void* d_out, int out_size)
{
    const float* x     = (const float*)d_in[0];
    const float* pos   = (const float*)d_in[1];
    const int*   batch = (const int*)d_in[2];
    const float* Wq    = (const float*)d_in[3];
    const float* bq    = (const float*)d_in[4];
    const float* Wv    = (const float*)d_in[5];
    const float* bv    = (const float*)d_in[6];
    const float* Wo    = (const float*)d_in[7];
    const float* bo    = (const float*)d_in[8];
    const float* freqs = (const float*)d_in[9];
    float* out = (float*)d_out;

    float *gq, *gv, *gk, *gbqv;
    __half *gxh, *gxl, *gah, *gal, *gwqvh, *gwoh;
    cudaGetSymbolAddress((void**)&gq, g_q);
    cudaGetSymbolAddress((void**)&gv, g_v);
    cudaGetSymbolAddress((void**)&gk, g_k);
    cudaGetSymbolAddress((void**)&gbqv, g_bqv);
    cudaGetSymbolAddress((void**)&gxh, g_xh);
    cudaGetSymbolAddress((void**)&gxl, g_xl);
    cudaGetSymbolAddress((void**)&gah, g_ah);
    cudaGetSymbolAddress((void**)&gal, g_al);
    cudaGetSymbolAddress((void**)&gwqvh, g_wqvh);
    cudaGetSymbolAddress((void**)&gwoh, g_woh);

    cudaFuncSetAttribute(gemm_mma,
                         cudaFuncAttributeMaxDynamicSharedMemorySize, GEMM_SMEM);

    // 1) fp16 hi/lo conversion of x; weight transpose (fp16)
    convert_x_kernel<<<(NN * CCH / 4 + 255) / 256, 256>>>(x);
    prep_w_kernel<<<(NQV * CCH + CCH * EE + 255) / 256, 256>>>(Wq, Wv, Wo, bq, bv);

    // 2) fused QV projection + RoPE epilogue -> g_q (rot), g_k (rot ones), g_v
    gemm_mma<<<dim3(NQV / 128, NN / 128), 256, GEMM_SMEM>>>(
        gxh, gxl, gwqvh, gbqv, gq, gv, gk, pos, freqs, CCH, 1);

    // 3) kv = segsum(k outer v) per node-split (raw; summed+scaled at use)
    kv_kernel<<<dim3(3 * KVSPLIT, NGRAPH), 256>>>(batch);

    // 4) attn = q . kv[batch]/512 -> fp16 hi/lo
    attn_kernel<<<dim3(16, NGRAPH), 256>>>(batch);

    // 5) out = attn @ Wo + bo
    gemm_mma<<<dim3(EE / 128, NN / 128), 256, GEMM_SMEM>>>(
        gah, gal, gwoh, bo, out, out, nullptr, nullptr, nullptr, EE, 0);
}